// round 4
// baseline (speedup 1.0000x reference)
#include <cuda_runtime.h>
#include <cstdint>

#define ALPHA 0.2f

// Scratch: max BT = 128 slices. g_WhT layout: [bt][d(128)][j(512)], tf32-rounded.
__device__ float g_WhT[128 * 128 * 512];
__device__ float g_es[128 * 512];
__device__ float g_ed[128 * 512];

// ---------------------------------------------------------------------------
// helpers
// ---------------------------------------------------------------------------
__device__ __forceinline__ float totf32(float x) {
    uint32_t r;
    asm("cvt.rna.tf32.f32 %0, %1;" : "=r"(r) : "f"(x));
    return __uint_as_float(r);
}

// FMA-pipe exp (no MUFU). Valid for |x| < ~60; here |x| <= ~5.
__device__ __forceinline__ float fexp(float x) {
    float y = fmaf(x, 1.4426950408889634f, 12582912.0f);   // round-to-nearest int
    float f = fmaf(x, 1.4426950408889634f, -(y - 12582912.0f));
    float p = 1.3333558146e-3f;
    p = fmaf(p, f, 9.6181291076e-3f);
    p = fmaf(p, f, 5.5504108664e-2f);
    p = fmaf(p, f, 2.4022650695e-1f);
    p = fmaf(p, f, 6.9314718056e-1f);
    p = fmaf(p, f, 1.0f);
    int ni = __float_as_int(y) - 0x4B400000;
    return __int_as_float(__float_as_int(p) + (ni << 23));
}

__device__ __forceinline__ void mma_tf32(float* d, const uint32_t* a, const uint32_t* b) {
    asm volatile(
        "mma.sync.aligned.m16n8k8.row.col.f32.tf32.tf32.f32 "
        "{%0,%1,%2,%3}, {%4,%5,%6,%7}, {%8,%9}, {%0,%1,%2,%3};"
        : "+f"(d[0]), "+f"(d[1]), "+f"(d[2]), "+f"(d[3])
        : "r"(a[0]), "r"(a[1]), "r"(a[2]), "r"(a[3]), "r"(b[0]), "r"(b[1]));
}

// ---------------------------------------------------------------------------
// Kernel A: Wh = h @ W (fp32), fused es/ed dots; writes Wh TRANSPOSED,
// tf32-rounded, per bt slice: g_WhT[s][c][j].
// ---------------------------------------------------------------------------
__global__ __launch_bounds__(256, 2)
void gat_wh_kernel(const float* __restrict__ h, const float* __restrict__ W,
                   const float* __restrict__ a) {
    __shared__ float Ws[32 * 132];
    __shared__ float hs[64 * 33];
    __shared__ float a_sh[256];

    int t = threadIdx.x;
    int rg = t >> 3;
    int cg = t & 7;
    long brow = (long)blockIdx.x * 64;
    int slice = blockIdx.x >> 3;
    int jloc = (blockIdx.x & 7) * 64 + rg;   // row within slice for acc0

    a_sh[t] = a[t];

    float acc0[16], acc1[16];
#pragma unroll
    for (int i = 0; i < 16; i++) { acc0[i] = 0.f; acc1[i] = 0.f; }

    for (int kt = 0; kt < 4; kt++) {
        __syncthreads();
        {
            const float4* Wg = (const float4*)(W + kt * 32 * 128);
            float4* Wd = (float4*)Ws;
#pragma unroll
            for (int m = 0; m < 4; m++) {
                int idx = t + m * 256;
                int r = idx >> 5, w = idx & 31;
                Wd[r * 33 + w] = Wg[r * 32 + w];
            }
        }
#pragma unroll
        for (int m = 0; m < 8; m++) {
            int idx = t + m * 256;
            int r = idx >> 5, k = idx & 31;
            hs[r * 33 + k] = h[(brow + r) * 128 + kt * 32 + k];
        }
        __syncthreads();

        const float4* Wv = (const float4*)Ws;
#pragma unroll 4
        for (int k = 0; k < 32; k++) {
            float hv0 = hs[rg * 33 + k];
            float hv1 = hs[(rg + 32) * 33 + k];
#pragma unroll
            for (int q = 0; q < 4; q++) {
                float4 w4 = Wv[k * 33 + cg + 8 * q];
                acc0[q * 4 + 0] += hv0 * w4.x; acc0[q * 4 + 1] += hv0 * w4.y;
                acc0[q * 4 + 2] += hv0 * w4.z; acc0[q * 4 + 3] += hv0 * w4.w;
                acc1[q * 4 + 0] += hv1 * w4.x; acc1[q * 4 + 1] += hv1 * w4.y;
                acc1[q * 4 + 2] += hv1 * w4.z; acc1[q * 4 + 3] += hv1 * w4.w;
            }
        }
    }

    // Epilogue: transposed tf32 stores + es/ed dots (full precision).
    float* WhT = g_WhT + (long)slice * 128 * 512;
    float s0 = 0.f, s1 = 0.f, d0 = 0.f, d1 = 0.f;
#pragma unroll
    for (int q = 0; q < 4; q++) {
#pragma unroll
        for (int e = 0; e < 4; e++) {
            int c = 4 * cg + 32 * q + e;
            float v0 = acc0[q * 4 + e], v1 = acc1[q * 4 + e];
            WhT[(long)c * 512 + jloc]      = totf32(v0);
            WhT[(long)c * 512 + jloc + 32] = totf32(v1);
            float as = a_sh[c], ad = a_sh[128 + c];
            s0 += v0 * as; d0 += v0 * ad;
            s1 += v1 * as; d1 += v1 * ad;
        }
    }
#pragma unroll
    for (int o = 4; o >= 1; o >>= 1) {
        s0 += __shfl_xor_sync(0xffffffffu, s0, o);
        d0 += __shfl_xor_sync(0xffffffffu, d0, o);
        s1 += __shfl_xor_sync(0xffffffffu, s1, o);
        d1 += __shfl_xor_sync(0xffffffffu, d1, o);
    }
    if (cg == 0) {
        g_es[brow + rg] = s0;       g_ed[brow + rg] = d0;
        g_es[brow + rg + 32] = s1;  g_ed[brow + rg + 32] = d1;
    }
}

// ---------------------------------------------------------------------------
// Kernel B: D[128i x 128d] = P[128 x 512] @ Wh[512 x 128] via mma.sync tf32.
// P = adj ? exp(leaky_relu(es_i + ed_j)) : 0  (no max shift; |e| small).
// B operand loaded directly from g_WhT (L1-resident); only P tile in smem.
// smem = Ps[128][132] + l[128]  (~68.5KB) -> 2 CTAs/SM.
// ---------------------------------------------------------------------------
static constexpr int SP = 132;
static constexpr int SMEM_ATTN = (128 * SP + 128) * 4;

__global__ __launch_bounds__(256, 2)
void gat_attn_mma(const int* __restrict__ adj, float* __restrict__ out) {
    extern __shared__ float sm[];
    float* Ps  = sm;
    float* l_sh = sm + 128 * SP;
    const uint32_t* Pu = (const uint32_t*)Ps;

    int t = threadIdx.x;
    int w = t >> 5;
    int l = t & 31;
    int bt = blockIdx.x >> 2;
    int ibase = (blockIdx.x & 3) * 128;
    long rowbase = (long)bt * 512;

    if (t < 128) l_sh[t] = 0.f;

    // P-build mapping: row i = 16*w + (l>>1), j half = (l&1)*64
    int i_row = 16 * w + (l >> 1);
    int jbase = (l & 1) * 64;
    float es_i = g_es[rowbase + ibase + i_row];

    // MMA mapping: warp (wm, wn) covers rows wm*32..+32, cols wn*64..+64
    int wm = w >> 1, wn = w & 1;
    int gid = l >> 2, tig = l & 3;

    const float* WhT = g_WhT + (long)bt * 128 * 512;

    float acc[2][8][4];
#pragma unroll
    for (int mt = 0; mt < 2; mt++)
#pragma unroll
        for (int nt = 0; nt < 8; nt++)
#pragma unroll
            for (int e = 0; e < 4; e++) acc[mt][nt][e] = 0.f;

    for (int jt = 0; jt < 4; jt++) {
        __syncthreads();   // prev MMA done reading Ps (and init visible at jt=0)

        // --- Build P tile (tf32-rounded into smem) + row sums ---
        {
            float lsum = 0.f;
            const int* arow = adj + (long)(ibase + i_row) * 512 + jt * 128 + jbase;
            const float4* edp = (const float4*)(g_ed + rowbase + jt * 128 + jbase);
#pragma unroll
            for (int c = 0; c < 16; c++) {
                int4 av = *(const int4*)(arow + 4 * c);
                float4 edv = __ldg(edp + c);
                float x, p0, p1, p2, p3;
                x = es_i + edv.x; x = fmaxf(x, ALPHA * x); p0 = (av.x > 0) ? fexp(x) : 0.f;
                x = es_i + edv.y; x = fmaxf(x, ALPHA * x); p1 = (av.y > 0) ? fexp(x) : 0.f;
                x = es_i + edv.z; x = fmaxf(x, ALPHA * x); p2 = (av.z > 0) ? fexp(x) : 0.f;
                x = es_i + edv.w; x = fmaxf(x, ALPHA * x); p3 = (av.w > 0) ? fexp(x) : 0.f;
                lsum += p0 + p1 + p2 + p3;
                float4 pv = make_float4(totf32(p0), totf32(p1), totf32(p2), totf32(p3));
                *(float4*)(Ps + i_row * SP + jbase + 4 * c) = pv;
            }
            lsum += __shfl_xor_sync(0xffffffffu, lsum, 1);
            if ((l & 1) == 0) l_sh[i_row] += lsum;
        }
        __syncthreads();   // Ps ready

        // --- MMA: 16 k-steps of 8; A from smem, B straight from g_WhT (L1) ---
        const float* Bbase = WhT + jt * 128 + tig;
#pragma unroll 4
        for (int ks = 0; ks < 16; ks++) {
            int k0 = ks * 8;
            uint32_t A[2][4];
#pragma unroll
            for (int mt = 0; mt < 2; mt++) {
                int rb = wm * 32 + mt * 16;
                A[mt][0] = Pu[(rb + gid) * SP + k0 + tig];
                A[mt][1] = Pu[(rb + gid + 8) * SP + k0 + tig];
                A[mt][2] = Pu[(rb + gid) * SP + k0 + tig + 4];
                A[mt][3] = Pu[(rb + gid + 8) * SP + k0 + tig + 4];
            }
            uint32_t Bf[8][2];
#pragma unroll
            for (int nt = 0; nt < 8; nt++) {
                int nb = wn * 64 + nt * 8;
                const float* bp = Bbase + (long)(nb + gid) * 512 + k0;
                Bf[nt][0] = __float_as_uint(__ldg(bp));
                Bf[nt][1] = __float_as_uint(__ldg(bp + 4));
            }
#pragma unroll
            for (int mt = 0; mt < 2; mt++)
#pragma unroll
                for (int nt = 0; nt < 8; nt++)
                    mma_tf32(acc[mt][nt], A[mt], Bf[nt]);
        }
    }

    // Epilogue: out = acc / l.
#pragma unroll
    for (int mt = 0; mt < 2; mt++) {
        int rb = wm * 32 + mt * 16;
        float inv0 = 1.f / l_sh[rb + gid];
        float inv1 = 1.f / l_sh[rb + gid + 8];
        long row0 = rowbase + ibase + rb + gid;
        long row1 = row0 + 8;
#pragma unroll
        for (int nt = 0; nt < 8; nt++) {
            int col = wn * 64 + nt * 8 + 2 * tig;
            *(float2*)(out + row0 * 128 + col) =
                make_float2(acc[mt][nt][0] * inv0, acc[mt][nt][1] * inv0);
            *(float2*)(out + row1 * 128 + col) =
                make_float2(acc[mt][nt][2] * inv1, acc[mt][nt][3] * inv1);
        }
    }
}

extern "C" void kernel_launch(void* const* d_in, const int* in_sizes, int n_in,
                              void* d_out, int out_size) {
    const float* h   = (const float*)d_in[0];
    const int*   adj = (const int*)d_in[1];
    const float* W   = (const float*)d_in[2];
    const float* a   = (const float*)d_in[3];
    float* out = (float*)d_out;

    int BT = in_sizes[0] / (512 * 128);
    if (BT > 128) BT = 128;

    cudaFuncSetAttribute(gat_attn_mma,
                         cudaFuncAttributeMaxDynamicSharedMemorySize, SMEM_ATTN);

    gat_wh_kernel<<<BT * 8, 256>>>(h, W, a);
    gat_attn_mma<<<BT * 4, 256, SMEM_ATTN>>>(adj, out);
}

// round 5
// speedup vs baseline: 1.2923x; 1.2923x over previous
#include <cuda_runtime.h>
#include <cstdint>

#define ALPHA 0.2f

// Scratch: max BT = 128 slices. g_WhT layout: [bt][d(128)][j(512)], tf32-rounded.
__device__ float g_WhT[128 * 128 * 512];
__device__ float g_es[128 * 512];
__device__ float g_ed[128 * 512];

// ---------------------------------------------------------------------------
// helpers
// ---------------------------------------------------------------------------
__device__ __forceinline__ float totf32(float x) {
    uint32_t r;
    asm("cvt.rna.tf32.f32 %0, %1;" : "=r"(r) : "f"(x));
    return __uint_as_float(r);
}

// FMA-pipe exp (no MUFU). Valid for |x| < ~60; here |x| <= ~5.
__device__ __forceinline__ float fexp(float x) {
    float y = fmaf(x, 1.4426950408889634f, 12582912.0f);   // round-to-nearest int
    float f = fmaf(x, 1.4426950408889634f, -(y - 12582912.0f));
    float p = 1.3333558146e-3f;
    p = fmaf(p, f, 9.6181291076e-3f);
    p = fmaf(p, f, 5.5504108664e-2f);
    p = fmaf(p, f, 2.4022650695e-1f);
    p = fmaf(p, f, 6.9314718056e-1f);
    p = fmaf(p, f, 1.0f);
    int ni = __float_as_int(y) - 0x4B400000;
    return __int_as_float(__float_as_int(p) + (ni << 23));
}

__device__ __forceinline__ void mma_tf32(float* d, const uint32_t* a, const uint32_t* b) {
    asm volatile(
        "mma.sync.aligned.m16n8k8.row.col.f32.tf32.tf32.f32 "
        "{%0,%1,%2,%3}, {%4,%5,%6,%7}, {%8,%9}, {%0,%1,%2,%3};"
        : "+f"(d[0]), "+f"(d[1]), "+f"(d[2]), "+f"(d[3])
        : "r"(a[0]), "r"(a[1]), "r"(a[2]), "r"(a[3]), "r"(b[0]), "r"(b[1]));
}

// ---------------------------------------------------------------------------
// Kernel A: Wh = h @ W (fp32), fused es/ed dots; writes Wh TRANSPOSED,
// tf32-rounded, per bt slice: g_WhT[s][c][j].
// ---------------------------------------------------------------------------
__global__ __launch_bounds__(256, 2)
void gat_wh_kernel(const float* __restrict__ h, const float* __restrict__ W,
                   const float* __restrict__ a) {
    __shared__ float Ws[32 * 132];
    __shared__ float hs[64 * 33];
    __shared__ float a_sh[256];

    int t = threadIdx.x;
    int rg = t >> 3;
    int cg = t & 7;
    long brow = (long)blockIdx.x * 64;
    int slice = blockIdx.x >> 3;
    int jloc = (blockIdx.x & 7) * 64 + rg;   // row within slice for acc0

    a_sh[t] = a[t];

    float acc0[16], acc1[16];
#pragma unroll
    for (int i = 0; i < 16; i++) { acc0[i] = 0.f; acc1[i] = 0.f; }

    for (int kt = 0; kt < 4; kt++) {
        __syncthreads();
        {
            const float4* Wg = (const float4*)(W + kt * 32 * 128);
            float4* Wd = (float4*)Ws;
#pragma unroll
            for (int m = 0; m < 4; m++) {
                int idx = t + m * 256;
                int r = idx >> 5, w = idx & 31;
                Wd[r * 33 + w] = Wg[r * 32 + w];
            }
        }
#pragma unroll
        for (int m = 0; m < 8; m++) {
            int idx = t + m * 256;
            int r = idx >> 5, k = idx & 31;
            hs[r * 33 + k] = h[(brow + r) * 128 + kt * 32 + k];
        }
        __syncthreads();

        const float4* Wv = (const float4*)Ws;
#pragma unroll 4
        for (int k = 0; k < 32; k++) {
            float hv0 = hs[rg * 33 + k];
            float hv1 = hs[(rg + 32) * 33 + k];
#pragma unroll
            for (int q = 0; q < 4; q++) {
                float4 w4 = Wv[k * 33 + cg + 8 * q];
                acc0[q * 4 + 0] += hv0 * w4.x; acc0[q * 4 + 1] += hv0 * w4.y;
                acc0[q * 4 + 2] += hv0 * w4.z; acc0[q * 4 + 3] += hv0 * w4.w;
                acc1[q * 4 + 0] += hv1 * w4.x; acc1[q * 4 + 1] += hv1 * w4.y;
                acc1[q * 4 + 2] += hv1 * w4.z; acc1[q * 4 + 3] += hv1 * w4.w;
            }
        }
    }

    // Epilogue: transposed tf32 stores + es/ed dots (full precision).
    float* WhT = g_WhT + (long)slice * 128 * 512;
    float s0 = 0.f, s1 = 0.f, d0 = 0.f, d1 = 0.f;
#pragma unroll
    for (int q = 0; q < 4; q++) {
#pragma unroll
        for (int e = 0; e < 4; e++) {
            int c = 4 * cg + 32 * q + e;
            float v0 = acc0[q * 4 + e], v1 = acc1[q * 4 + e];
            WhT[(long)c * 512 + jloc]      = totf32(v0);
            WhT[(long)c * 512 + jloc + 32] = totf32(v1);
            float as = a_sh[c], ad = a_sh[128 + c];
            s0 += v0 * as; d0 += v0 * ad;
            s1 += v1 * as; d1 += v1 * ad;
        }
    }
#pragma unroll
    for (int o = 4; o >= 1; o >>= 1) {
        s0 += __shfl_xor_sync(0xffffffffu, s0, o);
        d0 += __shfl_xor_sync(0xffffffffu, d0, o);
        s1 += __shfl_xor_sync(0xffffffffu, s1, o);
        d1 += __shfl_xor_sync(0xffffffffu, d1, o);
    }
    if (cg == 0) {
        g_es[brow + rg] = s0;       g_ed[brow + rg] = d0;
        g_es[brow + rg + 32] = s1;  g_ed[brow + rg + 32] = d1;
    }
}

// ---------------------------------------------------------------------------
// Kernel B: D[128i x 128d] = P[128 x 512] @ Wh[512 x 128] via mma.sync tf32.
// 512 threads / 16 warps; warp tile 32x32. Both operands in smem:
//   Ps[128][132] (i,k), Bs[128][132] (d,k) staged coalesced from g_WhT.
// P = adj ? exp(leaky_relu(es_i + ed_j)) : 0 ; l_i = sum_j P ; out = D / l.
// ---------------------------------------------------------------------------
static constexpr int SP = 132;
static constexpr int BS_OFF = 128 * SP;
static constexpr int L_OFF  = 2 * 128 * SP;
static constexpr int SMEM_ATTN = (L_OFF + 128) * 4;   // 135,680 B

__global__ __launch_bounds__(512, 1)
void gat_attn_mma(const int* __restrict__ adj, float* __restrict__ out) {
    extern __shared__ float sm[];
    float* Ps = sm;
    float* Bs = sm + BS_OFF;
    float* l_sh = sm + L_OFF;
    const uint32_t* Pu = (const uint32_t*)Ps;
    const uint32_t* Bu = (const uint32_t*)Bs;

    int t = threadIdx.x;
    int w = t >> 5;
    int l = t & 31;
    int bt = blockIdx.x >> 2;
    int ibase = (blockIdx.x & 3) * 128;
    long rowbase = (long)bt * 512;

    if (t < 128) l_sh[t] = 0.f;

    // P-build mapping: thread t -> row t>>2, j quarter (t&3)*32
    int i_row = t >> 2;
    int jbase = (t & 3) * 32;
    float es_i = g_es[rowbase + ibase + i_row];

    // MMA mapping: warp (wm = w>>2, wn = w&3): rows wm*32..+32, cols wn*32..+32
    int wm = w >> 2, wn = w & 3;
    int gid = l >> 2, tig = l & 3;

    const float* WhT = g_WhT + (long)bt * 128 * 512;

    float acc[2][4][4];
#pragma unroll
    for (int mt = 0; mt < 2; mt++)
#pragma unroll
        for (int nt = 0; nt < 4; nt++)
#pragma unroll
            for (int e = 0; e < 4; e++) acc[mt][nt][e] = 0.f;

    for (int jt = 0; jt < 4; jt++) {
        __syncthreads();   // prev MMA done reading Ps/Bs (init visible at jt=0)

        // --- Stage Bs[d][k] = g_WhT[d][jt*128 + k] (coalesced float4 copy) ---
        {
#pragma unroll
            for (int m = 0; m < 8; m++) {
                int idx = t + m * 512;           // 0..4095 float4s
                int d = idx >> 5, c4 = idx & 31;
                float4 v = *(const float4*)(WhT + (long)d * 512 + jt * 128 + 4 * c4);
                *(float4*)(Bs + d * SP + 4 * c4) = v;
            }
        }

        // --- Build P tile (tf32-rounded) + row sums ---
        {
            float lsum = 0.f;
            const int* arow = adj + (long)(ibase + i_row) * 512 + jt * 128 + jbase;
            const float4* edp = (const float4*)(g_ed + rowbase + jt * 128 + jbase);
#pragma unroll
            for (int c = 0; c < 8; c++) {
                int4 av = *(const int4*)(arow + 4 * c);
                float4 edv = __ldg(edp + c);
                float x, p0, p1, p2, p3;
                x = es_i + edv.x; x = fmaxf(x, ALPHA * x); p0 = (av.x > 0) ? fexp(x) : 0.f;
                x = es_i + edv.y; x = fmaxf(x, ALPHA * x); p1 = (av.y > 0) ? fexp(x) : 0.f;
                x = es_i + edv.z; x = fmaxf(x, ALPHA * x); p2 = (av.z > 0) ? fexp(x) : 0.f;
                x = es_i + edv.w; x = fmaxf(x, ALPHA * x); p3 = (av.w > 0) ? fexp(x) : 0.f;
                lsum += p0 + p1 + p2 + p3;
                float4 pv = make_float4(totf32(p0), totf32(p1), totf32(p2), totf32(p3));
                *(float4*)(Ps + i_row * SP + jbase + 4 * c) = pv;
            }
            lsum += __shfl_xor_sync(0xffffffffu, lsum, 1);
            lsum += __shfl_xor_sync(0xffffffffu, lsum, 2);
            if ((t & 3) == 0) l_sh[i_row] += lsum;
        }
        __syncthreads();   // Ps + Bs ready

        // --- MMA: 16 k-steps of 8 ---
#pragma unroll 4
        for (int ks = 0; ks < 16; ks++) {
            int k0 = ks * 8;
            uint32_t A[2][4];
#pragma unroll
            for (int mt = 0; mt < 2; mt++) {
                int rb = wm * 32 + mt * 16;
                A[mt][0] = Pu[(rb + gid) * SP + k0 + tig];
                A[mt][1] = Pu[(rb + gid + 8) * SP + k0 + tig];
                A[mt][2] = Pu[(rb + gid) * SP + k0 + tig + 4];
                A[mt][3] = Pu[(rb + gid + 8) * SP + k0 + tig + 4];
            }
            uint32_t Bf[4][2];
#pragma unroll
            for (int nt = 0; nt < 4; nt++) {
                int nb = wn * 32 + nt * 8;
                Bf[nt][0] = Bu[(nb + gid) * SP + k0 + tig];
                Bf[nt][1] = Bu[(nb + gid) * SP + k0 + tig + 4];
            }
#pragma unroll
            for (int mt = 0; mt < 2; mt++)
#pragma unroll
                for (int nt = 0; nt < 4; nt++)
                    mma_tf32(acc[mt][nt], A[mt], Bf[nt]);
        }
    }

    // Epilogue: out = acc / l.
#pragma unroll
    for (int mt = 0; mt < 2; mt++) {
        int rb = wm * 32 + mt * 16;
        float inv0 = 1.f / l_sh[rb + gid];
        float inv1 = 1.f / l_sh[rb + gid + 8];
        long row0 = rowbase + ibase + rb + gid;
        long row1 = row0 + 8;
#pragma unroll
        for (int nt = 0; nt < 4; nt++) {
            int col = wn * 32 + nt * 8 + 2 * tig;
            *(float2*)(out + row0 * 128 + col) =
                make_float2(acc[mt][nt][0] * inv0, acc[mt][nt][1] * inv0);
            *(float2*)(out + row1 * 128 + col) =
                make_float2(acc[mt][nt][2] * inv1, acc[mt][nt][3] * inv1);
        }
    }
}

extern "C" void kernel_launch(void* const* d_in, const int* in_sizes, int n_in,
                              void* d_out, int out_size) {
    const float* h   = (const float*)d_in[0];
    const int*   adj = (const int*)d_in[1];
    const float* W   = (const float*)d_in[2];
    const float* a   = (const float*)d_in[3];
    float* out = (float*)d_out;

    int BT = in_sizes[0] / (512 * 128);
    if (BT > 128) BT = 128;

    cudaFuncSetAttribute(gat_attn_mma,
                         cudaFuncAttributeMaxDynamicSharedMemorySize, SMEM_ATTN);

    gat_wh_kernel<<<BT * 8, 256>>>(h, W, a);
    gat_attn_mma<<<BT * 4, 512, SMEM_ATTN>>>(adj, out);
}

// round 6
// speedup vs baseline: 1.4815x; 1.1464x over previous
#include <cuda_runtime.h>
#include <cuda_fp16.h>
#include <cstdint>

#define ALPHA 0.2f

// Scratch: max BT = 128 slices. g_WhT layout: [bt][d(128)][j(512)], fp16.
__device__ __half g_WhT[128 * 128 * 512];
__device__ float g_es[128 * 512];
__device__ float g_ed[128 * 512];

// ---------------------------------------------------------------------------
// helpers
// ---------------------------------------------------------------------------
// FMA-pipe exp (no MUFU). Valid for |x| < ~60; here |x| <= ~5.
__device__ __forceinline__ float fexp(float x) {
    float y = fmaf(x, 1.4426950408889634f, 12582912.0f);   // round-to-nearest int
    float f = fmaf(x, 1.4426950408889634f, -(y - 12582912.0f));
    float p = 1.3333558146e-3f;
    p = fmaf(p, f, 9.6181291076e-3f);
    p = fmaf(p, f, 5.5504108664e-2f);
    p = fmaf(p, f, 2.4022650695e-1f);
    p = fmaf(p, f, 6.9314718056e-1f);
    p = fmaf(p, f, 1.0f);
    int ni = __float_as_int(y) - 0x4B400000;
    return __int_as_float(__float_as_int(p) + (ni << 23));
}

__device__ __forceinline__ void mma_f16(float* d, const uint32_t* a, const uint32_t* b) {
    asm volatile(
        "mma.sync.aligned.m16n8k16.row.col.f32.f16.f16.f32 "
        "{%0,%1,%2,%3}, {%4,%5,%6,%7}, {%8,%9}, {%0,%1,%2,%3};"
        : "+f"(d[0]), "+f"(d[1]), "+f"(d[2]), "+f"(d[3])
        : "r"(a[0]), "r"(a[1]), "r"(a[2]), "r"(a[3]), "r"(b[0]), "r"(b[1]));
}

// ---------------------------------------------------------------------------
// Kernel A: Wh = h @ W (fp32), fused es/ed dots; writes Wh TRANSPOSED as fp16:
// g_WhT[s][c][j]. es/ed from full-precision accumulators.
// ---------------------------------------------------------------------------
__global__ __launch_bounds__(256, 2)
void gat_wh_kernel(const float* __restrict__ h, const float* __restrict__ W,
                   const float* __restrict__ a) {
    __shared__ float Ws[32 * 132];
    __shared__ float hs[64 * 33];
    __shared__ float a_sh[256];

    int t = threadIdx.x;
    int rg = t >> 3;
    int cg = t & 7;
    long brow = (long)blockIdx.x * 64;
    int slice = blockIdx.x >> 3;
    int jloc = (blockIdx.x & 7) * 64 + rg;

    a_sh[t] = a[t];

    float acc0[16], acc1[16];
#pragma unroll
    for (int i = 0; i < 16; i++) { acc0[i] = 0.f; acc1[i] = 0.f; }

    for (int kt = 0; kt < 4; kt++) {
        __syncthreads();
        {
            const float4* Wg = (const float4*)(W + kt * 32 * 128);
            float4* Wd = (float4*)Ws;
#pragma unroll
            for (int m = 0; m < 4; m++) {
                int idx = t + m * 256;
                int r = idx >> 5, w = idx & 31;
                Wd[r * 33 + w] = Wg[r * 32 + w];
            }
        }
#pragma unroll
        for (int m = 0; m < 8; m++) {
            int idx = t + m * 256;
            int r = idx >> 5, k = idx & 31;
            hs[r * 33 + k] = h[(brow + r) * 128 + kt * 32 + k];
        }
        __syncthreads();

        const float4* Wv = (const float4*)Ws;
#pragma unroll 4
        for (int k = 0; k < 32; k++) {
            float hv0 = hs[rg * 33 + k];
            float hv1 = hs[(rg + 32) * 33 + k];
#pragma unroll
            for (int q = 0; q < 4; q++) {
                float4 w4 = Wv[k * 33 + cg + 8 * q];
                acc0[q * 4 + 0] += hv0 * w4.x; acc0[q * 4 + 1] += hv0 * w4.y;
                acc0[q * 4 + 2] += hv0 * w4.z; acc0[q * 4 + 3] += hv0 * w4.w;
                acc1[q * 4 + 0] += hv1 * w4.x; acc1[q * 4 + 1] += hv1 * w4.y;
                acc1[q * 4 + 2] += hv1 * w4.z; acc1[q * 4 + 3] += hv1 * w4.w;
            }
        }
    }

    __half* WhT = g_WhT + (long)slice * 128 * 512;
    float s0 = 0.f, s1 = 0.f, d0 = 0.f, d1 = 0.f;
#pragma unroll
    for (int q = 0; q < 4; q++) {
#pragma unroll
        for (int e = 0; e < 4; e++) {
            int c = 4 * cg + 32 * q + e;
            float v0 = acc0[q * 4 + e], v1 = acc1[q * 4 + e];
            WhT[(long)c * 512 + jloc]      = __float2half_rn(v0);
            WhT[(long)c * 512 + jloc + 32] = __float2half_rn(v1);
            float as = a_sh[c], ad = a_sh[128 + c];
            s0 += v0 * as; d0 += v0 * ad;
            s1 += v1 * as; d1 += v1 * ad;
        }
    }
#pragma unroll
    for (int o = 4; o >= 1; o >>= 1) {
        s0 += __shfl_xor_sync(0xffffffffu, s0, o);
        d0 += __shfl_xor_sync(0xffffffffu, d0, o);
        s1 += __shfl_xor_sync(0xffffffffu, s1, o);
        d1 += __shfl_xor_sync(0xffffffffu, d1, o);
    }
    if (cg == 0) {
        g_es[brow + rg] = s0;       g_ed[brow + rg] = d0;
        g_es[brow + rg + 32] = s1;  g_ed[brow + rg + 32] = d1;
    }
}

// ---------------------------------------------------------------------------
// Kernel B: D[128i x 128d] = P[128 x 512] @ Wh[512 x 128] via mma.sync
// m16n8k16 fp16 (fp32 accum). 512 threads / 16 warps; warp tile 32x32.
// Ps/Bs in smem as half2 (u32) with stride 68 u32 -> conflict-free fragments.
// Bs staged via cp.async (latency hidden behind P-build).
// P = adj ? exp(leaky_relu(es_i + ed_j)) : 0 ; l_i = sum_j P ; out = D / l.
// ---------------------------------------------------------------------------
static constexpr int SPH = 68;                        // u32 (half2) stride
static constexpr int SMEM_ATTN = (2 * 128 * SPH + 128) * 4;   // 70,144 B

__global__ __launch_bounds__(512, 1)
void gat_attn_mma(const int* __restrict__ adj, float* __restrict__ out) {
    extern __shared__ uint32_t smu[];
    uint32_t* Ps = smu;                     // 128 x 68
    uint32_t* Bs = smu + 128 * SPH;         // 128 x 68
    float* l_sh = (float*)(smu + 2 * 128 * SPH);

    int t = threadIdx.x;
    int w = t >> 5;
    int l = t & 31;
    int bt = blockIdx.x >> 2;
    int ibase = (blockIdx.x & 3) * 128;
    long rowbase = (long)bt * 512;

    if (t < 128) l_sh[t] = 0.f;

    // P-build mapping: thread t -> row t>>2, j quarter (t&3)*32
    int i_row = t >> 2;
    int jbase = (t & 3) * 32;
    int kkb = (t & 3) * 16;                 // half2 index of this thread's span
    float es_i = g_es[rowbase + ibase + i_row];

    // MMA mapping: warp (wm = w>>2, wn = w&3): rows wm*32..+32, cols wn*32..+32
    int wm = w >> 2, wn = w & 3;
    int gid = l >> 2, tig = l & 3;

    const __half* WhT = g_WhT + (long)bt * 128 * 512;

    uint32_t bs_addr;
    asm("{ .reg .u64 tt; cvta.to.shared.u64 tt, %1; cvt.u32.u64 %0, tt; }"
        : "=r"(bs_addr) : "l"((const void*)Bs));

    float acc[2][4][4];
#pragma unroll
    for (int mt = 0; mt < 2; mt++)
#pragma unroll
        for (int nt = 0; nt < 4; nt++)
#pragma unroll
            for (int e = 0; e < 4; e++) acc[mt][nt][e] = 0.f;

    for (int jt = 0; jt < 4; jt++) {
        __syncthreads();   // prev MMA done reading Ps/Bs (init visible at jt=0)

        // --- Stage Bs[d][kk] via cp.async (16B = 8 halves per chunk) ---
#pragma unroll
        for (int m = 0; m < 4; m++) {
            int idx = t + m * 512;          // 0..2047
            int d = idx >> 4;               // 128 rows
            int ch = idx & 15;              // 16 chunks of 16B per row
            uint32_t dst = bs_addr + (uint32_t)(d * SPH * 4 + ch * 16);
            const void* src = WhT + (long)d * 512 + jt * 128 + ch * 8;
            asm volatile("cp.async.ca.shared.global [%0], [%1], 16;" :: "r"(dst), "l"(src));
        }
        asm volatile("cp.async.commit_group;" ::: "memory");

        // --- Build P tile (fp16 into smem) + row sums ---
        {
            float lsum = 0.f;
            const int* arow = adj + (long)(ibase + i_row) * 512 + jt * 128 + jbase;
            const float4* edp = (const float4*)(g_ed + rowbase + jt * 128 + jbase);
#pragma unroll
            for (int c = 0; c < 8; c++) {
                int4 av = *(const int4*)(arow + 4 * c);
                float4 edv = __ldg(edp + c);
                float x, p0, p1, p2, p3;
                x = es_i + edv.x; x = fmaxf(x, ALPHA * x); p0 = (av.x > 0) ? fexp(x) : 0.f;
                x = es_i + edv.y; x = fmaxf(x, ALPHA * x); p1 = (av.y > 0) ? fexp(x) : 0.f;
                x = es_i + edv.z; x = fmaxf(x, ALPHA * x); p2 = (av.z > 0) ? fexp(x) : 0.f;
                x = es_i + edv.w; x = fmaxf(x, ALPHA * x); p3 = (av.w > 0) ? fexp(x) : 0.f;
                lsum += p0 + p1 + p2 + p3;
                __half2 h01 = __float22half2_rn(make_float2(p0, p1));
                __half2 h23 = __float22half2_rn(make_float2(p2, p3));
                uint2 st;
                st.x = *(uint32_t*)&h01;
                st.y = *(uint32_t*)&h23;
                *(uint2*)&Ps[i_row * SPH + kkb + 2 * c] = st;
            }
            lsum += __shfl_xor_sync(0xffffffffu, lsum, 1);
            lsum += __shfl_xor_sync(0xffffffffu, lsum, 2);
            if ((t & 3) == 0) l_sh[i_row] += lsum;
        }
        asm volatile("cp.async.wait_group 0;" ::: "memory");
        __syncthreads();   // Ps + Bs ready

        // --- MMA: 8 k-steps of 16 (kk window of 8 per step) ---
#pragma unroll
        for (int ks = 0; ks < 8; ks++) {
            int k0 = ks * 8;
            uint32_t A[2][4];
#pragma unroll
            for (int mt = 0; mt < 2; mt++) {
                int rb = wm * 32 + mt * 16;
                A[mt][0] = Ps[(rb + gid) * SPH + k0 + tig];
                A[mt][1] = Ps[(rb + gid + 8) * SPH + k0 + tig];
                A[mt][2] = Ps[(rb + gid) * SPH + k0 + tig + 4];
                A[mt][3] = Ps[(rb + gid + 8) * SPH + k0 + tig + 4];
            }
            uint32_t Bf[4][2];
#pragma unroll
            for (int nt = 0; nt < 4; nt++) {
                int nb = wn * 32 + nt * 8;
                Bf[nt][0] = Bs[(nb + gid) * SPH + k0 + tig];
                Bf[nt][1] = Bs[(nb + gid) * SPH + k0 + tig + 4];
            }
#pragma unroll
            for (int mt = 0; mt < 2; mt++)
#pragma unroll
                for (int nt = 0; nt < 4; nt++)
                    mma_f16(acc[mt][nt], A[mt], Bf[nt]);
        }
    }

    // Epilogue: out = acc / l.
#pragma unroll
    for (int mt = 0; mt < 2; mt++) {
        int rb = wm * 32 + mt * 16;
        float inv0 = 1.f / l_sh[rb + gid];
        float inv1 = 1.f / l_sh[rb + gid + 8];
        long row0 = rowbase + ibase + rb + gid;
        long row1 = row0 + 8;
#pragma unroll
        for (int nt = 0; nt < 4; nt++) {
            int col = wn * 32 + nt * 8 + 2 * tig;
            *(float2*)(out + row0 * 128 + col) =
                make_float2(acc[mt][nt][0] * inv0, acc[mt][nt][1] * inv0);
            *(float2*)(out + row1 * 128 + col) =
                make_float2(acc[mt][nt][2] * inv1, acc[mt][nt][3] * inv1);
        }
    }
}

extern "C" void kernel_launch(void* const* d_in, const int* in_sizes, int n_in,
                              void* d_out, int out_size) {
    const float* h   = (const float*)d_in[0];
    const int*   adj = (const int*)d_in[1];
    const float* W   = (const float*)d_in[2];
    const float* a   = (const float*)d_in[3];
    float* out = (float*)d_out;

    int BT = in_sizes[0] / (512 * 128);
    if (BT > 128) BT = 128;

    cudaFuncSetAttribute(gat_attn_mma,
                         cudaFuncAttributeMaxDynamicSharedMemorySize, SMEM_ATTN);

    gat_wh_kernel<<<BT * 8, 256>>>(h, W, a);
    gat_attn_mma<<<BT * 4, 512, SMEM_ATTN>>>(adj, out);
}

// round 7
// speedup vs baseline: 1.5138x; 1.0218x over previous
#include <cuda_runtime.h>
#include <cuda_fp16.h>
#include <cstdint>

#define ALPHA 0.2f

// Scratch: max BT = 128 slices. g_WhT layout: [bt][d(128)][j(512)], fp16.
__device__ __half g_WhT[128 * 128 * 512];
__device__ float g_es[128 * 512];
__device__ float g_ed[128 * 512];

// ---------------------------------------------------------------------------
// helpers
// ---------------------------------------------------------------------------
// FMA-pipe exp (no MUFU). Valid for |x| < ~60; here |x| <= ~5.
__device__ __forceinline__ float fexp(float x) {
    float y = fmaf(x, 1.4426950408889634f, 12582912.0f);   // round-to-nearest int
    float f = fmaf(x, 1.4426950408889634f, -(y - 12582912.0f));
    float p = 1.3333558146e-3f;
    p = fmaf(p, f, 9.6181291076e-3f);
    p = fmaf(p, f, 5.5504108664e-2f);
    p = fmaf(p, f, 2.4022650695e-1f);
    p = fmaf(p, f, 6.9314718056e-1f);
    p = fmaf(p, f, 1.0f);
    int ni = __float_as_int(y) - 0x4B400000;
    return __int_as_float(__float_as_int(p) + (ni << 23));
}

__device__ __forceinline__ void mma_f16(float* d, const uint32_t* a, const uint32_t* b) {
    asm volatile(
        "mma.sync.aligned.m16n8k16.row.col.f32.f16.f16.f32 "
        "{%0,%1,%2,%3}, {%4,%5,%6,%7}, {%8,%9}, {%0,%1,%2,%3};"
        : "+f"(d[0]), "+f"(d[1]), "+f"(d[2]), "+f"(d[3])
        : "r"(a[0]), "r"(a[1]), "r"(a[2]), "r"(a[3]), "r"(b[0]), "r"(b[1]));
}

// ---------------------------------------------------------------------------
// Kernel A: Wh = h @ W (fp32), fused es/ed dots; writes Wh TRANSPOSED as fp16:
// g_WhT[s][c][j]. es/ed from full-precision accumulators.
// ---------------------------------------------------------------------------
__global__ __launch_bounds__(256, 2)
void gat_wh_kernel(const float* __restrict__ h, const float* __restrict__ W,
                   const float* __restrict__ a) {
    __shared__ float Ws[32 * 132];
    __shared__ float hs[64 * 33];
    __shared__ float a_sh[256];

    int t = threadIdx.x;
    int rg = t >> 3;
    int cg = t & 7;
    long brow = (long)blockIdx.x * 64;
    int slice = blockIdx.x >> 3;
    int jloc = (blockIdx.x & 7) * 64 + rg;

    a_sh[t] = a[t];

    float acc0[16], acc1[16];
#pragma unroll
    for (int i = 0; i < 16; i++) { acc0[i] = 0.f; acc1[i] = 0.f; }

    for (int kt = 0; kt < 4; kt++) {
        __syncthreads();
        {
            const float4* Wg = (const float4*)(W + kt * 32 * 128);
            float4* Wd = (float4*)Ws;
#pragma unroll
            for (int m = 0; m < 4; m++) {
                int idx = t + m * 256;
                int r = idx >> 5, w = idx & 31;
                Wd[r * 33 + w] = Wg[r * 32 + w];
            }
        }
#pragma unroll
        for (int m = 0; m < 8; m++) {
            int idx = t + m * 256;
            int r = idx >> 5, k = idx & 31;
            hs[r * 33 + k] = h[(brow + r) * 128 + kt * 32 + k];
        }
        __syncthreads();

        const float4* Wv = (const float4*)Ws;
#pragma unroll 4
        for (int k = 0; k < 32; k++) {
            float hv0 = hs[rg * 33 + k];
            float hv1 = hs[(rg + 32) * 33 + k];
#pragma unroll
            for (int q = 0; q < 4; q++) {
                float4 w4 = Wv[k * 33 + cg + 8 * q];
                acc0[q * 4 + 0] += hv0 * w4.x; acc0[q * 4 + 1] += hv0 * w4.y;
                acc0[q * 4 + 2] += hv0 * w4.z; acc0[q * 4 + 3] += hv0 * w4.w;
                acc1[q * 4 + 0] += hv1 * w4.x; acc1[q * 4 + 1] += hv1 * w4.y;
                acc1[q * 4 + 2] += hv1 * w4.z; acc1[q * 4 + 3] += hv1 * w4.w;
            }
        }
    }

    __half* WhT = g_WhT + (long)slice * 128 * 512;
    float s0 = 0.f, s1 = 0.f, d0 = 0.f, d1 = 0.f;
#pragma unroll
    for (int q = 0; q < 4; q++) {
#pragma unroll
        for (int e = 0; e < 4; e++) {
            int c = 4 * cg + 32 * q + e;
            float v0 = acc0[q * 4 + e], v1 = acc1[q * 4 + e];
            WhT[(long)c * 512 + jloc]      = __float2half_rn(v0);
            WhT[(long)c * 512 + jloc + 32] = __float2half_rn(v1);
            float as = a_sh[c], ad = a_sh[128 + c];
            s0 += v0 * as; d0 += v0 * ad;
            s1 += v1 * as; d1 += v1 * ad;
        }
    }
#pragma unroll
    for (int o = 4; o >= 1; o >>= 1) {
        s0 += __shfl_xor_sync(0xffffffffu, s0, o);
        d0 += __shfl_xor_sync(0xffffffffu, d0, o);
        s1 += __shfl_xor_sync(0xffffffffu, s1, o);
        d1 += __shfl_xor_sync(0xffffffffu, d1, o);
    }
    if (cg == 0) {
        g_es[brow + rg] = s0;       g_ed[brow + rg] = d0;
        g_es[brow + rg + 32] = s1;  g_ed[brow + rg + 32] = d1;
    }
}

// ---------------------------------------------------------------------------
// Kernel B: D[128i x 128d] = P[128 x 512] @ Wh[512 x 128], mma m16n8k16 fp16.
// Double-buffered Ps/Bs; role-alternating warps overlap P-build(jt+1) with
// MMA(jt); Bs staged by cp.async across the whole iteration body.
// ---------------------------------------------------------------------------
static constexpr int SPH = 68;                          // u32 (half2) stride
static constexpr int BUF = 128 * SPH;                   // u32 per buffer
static constexpr int SMEM_ATTN = (4 * BUF + 128) * 4;   // 139,776 B

__global__ __launch_bounds__(512, 1)
void gat_attn_mma(const int* __restrict__ adj, float* __restrict__ out) {
    extern __shared__ uint32_t smu[];
    uint32_t* Ps = smu;                 // 2 x (128 x 68)
    uint32_t* Bs = smu + 2 * BUF;       // 2 x (128 x 68)
    float* l_sh = (float*)(smu + 4 * BUF);

    int t = threadIdx.x;
    int w = t >> 5;
    int l = t & 31;
    int bt = blockIdx.x >> 2;
    int ibase = (blockIdx.x & 3) * 128;
    long rowbase = (long)bt * 512;

    if (t < 128) l_sh[t] = 0.f;

    // P-build mapping: thread t -> row t>>2, j quarter (t&3)*32
    int i_row = t >> 2;
    int jbase = (t & 3) * 32;
    int kkb = (t & 3) * 16;
    float es_i = g_es[rowbase + ibase + i_row];

    // MMA mapping: warp (wm = w>>2, wn = w&3)
    int wm = w >> 2, wn = w & 3;
    int gid = l >> 2, tig = l & 3;

    const __half* WhT = g_WhT + (long)bt * 128 * 512;

    uint32_t bs_addr;
    asm("{ .reg .u64 tt; cvta.to.shared.u64 tt, %1; cvt.u32.u64 %0, tt; }"
        : "=r"(bs_addr) : "l"((const void*)Bs));

    float acc[2][4][4];
#pragma unroll
    for (int mt = 0; mt < 2; mt++)
#pragma unroll
        for (int nt = 0; nt < 4; nt++)
#pragma unroll
            for (int e = 0; e < 4; e++) acc[mt][nt][e] = 0.f;

    auto stage_B = [&](int jt, int buf) {
#pragma unroll
        for (int m = 0; m < 4; m++) {
            int idx = t + m * 512;
            int d = idx >> 4, ch = idx & 15;
            uint32_t dst = bs_addr + (uint32_t)(buf * BUF * 4 + d * SPH * 4 + ch * 16);
            const void* src = WhT + (long)d * 512 + jt * 128 + ch * 8;
            asm volatile("cp.async.ca.shared.global [%0], [%1], 16;" :: "r"(dst), "l"(src));
        }
        asm volatile("cp.async.commit_group;" ::: "memory");
    };

    auto build_P = [&](int jt, int buf) {
        uint32_t* Pb = Ps + buf * BUF;
        float lsum = 0.f;
        const int* arow = adj + (long)(ibase + i_row) * 512 + jt * 128 + jbase;
        const float4* edp = (const float4*)(g_ed + rowbase + jt * 128 + jbase);
#pragma unroll
        for (int c = 0; c < 8; c++) {
            int4 av = *(const int4*)(arow + 4 * c);
            float4 edv = __ldg(edp + c);
            float x, p0, p1, p2, p3;
            x = es_i + edv.x; x = fmaxf(x, ALPHA * x); p0 = (av.x > 0) ? fexp(x) : 0.f;
            x = es_i + edv.y; x = fmaxf(x, ALPHA * x); p1 = (av.y > 0) ? fexp(x) : 0.f;
            x = es_i + edv.z; x = fmaxf(x, ALPHA * x); p2 = (av.z > 0) ? fexp(x) : 0.f;
            x = es_i + edv.w; x = fmaxf(x, ALPHA * x); p3 = (av.w > 0) ? fexp(x) : 0.f;
            lsum += p0 + p1 + p2 + p3;
            __half2 h01 = __float22half2_rn(make_float2(p0, p1));
            __half2 h23 = __float22half2_rn(make_float2(p2, p3));
            uint2 st;
            st.x = *(uint32_t*)&h01;
            st.y = *(uint32_t*)&h23;
            *(uint2*)&Pb[i_row * SPH + kkb + 2 * c] = st;
        }
        lsum += __shfl_xor_sync(0xffffffffu, lsum, 1);
        lsum += __shfl_xor_sync(0xffffffffu, lsum, 2);
        if ((t & 3) == 0) l_sh[i_row] += lsum;
    };

    auto do_mma = [&](int buf) {
        const uint32_t* Pb = Ps + buf * BUF;
        const uint32_t* Bb = Bs + buf * BUF;
#pragma unroll
        for (int ks = 0; ks < 8; ks++) {
            int k0 = ks * 8;
            uint32_t A[2][4];
#pragma unroll
            for (int mt = 0; mt < 2; mt++) {
                int rb = wm * 32 + mt * 16;
                A[mt][0] = Pb[(rb + gid) * SPH + k0 + tig];
                A[mt][1] = Pb[(rb + gid + 8) * SPH + k0 + tig];
                A[mt][2] = Pb[(rb + gid) * SPH + k0 + tig + 4];
                A[mt][3] = Pb[(rb + gid + 8) * SPH + k0 + tig + 4];
            }
            uint32_t Bf[4][2];
#pragma unroll
            for (int nt = 0; nt < 4; nt++) {
                int nb = wn * 32 + nt * 8;
                Bf[nt][0] = Bb[(nb + gid) * SPH + k0 + tig];
                Bf[nt][1] = Bb[(nb + gid) * SPH + k0 + tig + 4];
            }
#pragma unroll
            for (int mt = 0; mt < 2; mt++)
#pragma unroll
                for (int nt = 0; nt < 4; nt++)
                    mma_f16(acc[mt][nt], A[mt], Bf[nt]);
        }
    };

    // Prologue: stage Bs[0] + build Ps[0].
    stage_B(0, 0);
    build_P(0, 0);
    asm volatile("cp.async.wait_group 0;" ::: "memory");
    __syncthreads();

    for (int jt = 0; jt < 4; jt++) {
        int buf = jt & 1, nbuf = buf ^ 1;
        if (jt < 3) stage_B(jt + 1, nbuf);
        // Role alternation: half the warps MMA first, half build first.
        if (w & 1) {
            if (jt < 3) build_P(jt + 1, nbuf);
            do_mma(buf);
        } else {
            do_mma(buf);
            if (jt < 3) build_P(jt + 1, nbuf);
        }
        asm volatile("cp.async.wait_group 0;" ::: "memory");
        __syncthreads();
    }

    // Epilogue: out = acc / l.
#pragma unroll
    for (int mt = 0; mt < 2; mt++) {
        int rb = wm * 32 + mt * 16;
        float inv0 = 1.f / l_sh[rb + gid];
        float inv1 = 1.f / l_sh[rb + gid + 8];
        long row0 = rowbase + ibase + rb + gid;
        long row1 = row0 + 8;
#pragma unroll
        for (int nt = 0; nt < 4; nt++) {
            int col = wn * 32 + nt * 8 + 2 * tig;
            *(float2*)(out + row0 * 128 + col) =
                make_float2(acc[mt][nt][0] * inv0, acc[mt][nt][1] * inv0);
            *(float2*)(out + row1 * 128 + col) =
                make_float2(acc[mt][nt][2] * inv1, acc[mt][nt][3] * inv1);
        }
    }
}

extern "C" void kernel_launch(void* const* d_in, const int* in_sizes, int n_in,
                              void* d_out, int out_size) {
    const float* h   = (const float*)d_in[0];
    const int*   adj = (const int*)d_in[1];
    const float* W   = (const float*)d_in[2];
    const float* a   = (const float*)d_in[3];
    float* out = (float*)d_out;

    int BT = in_sizes[0] / (512 * 128);
    if (BT > 128) BT = 128;

    cudaFuncSetAttribute(gat_attn_mma,
                         cudaFuncAttributeMaxDynamicSharedMemorySize, SMEM_ATTN);

    gat_wh_kernel<<<BT * 8, 256>>>(h, W, a);
    gat_attn_mma<<<BT * 4, 512, SMEM_ATTN>>>(adj, out);
}

// round 8
// speedup vs baseline: 1.7780x; 1.1745x over previous
#include <cuda_runtime.h>
#include <cuda_fp16.h>
#include <cstdint>

#define ALPHA 0.2f

// Scratch: max BT = 128 slices. g_WhT layout: [bt][d(128)][j(512)], fp16.
__device__ __half g_WhT[128 * 128 * 512];
__device__ float g_es[128 * 512];
__device__ float g_ed[128 * 512];
__device__ uint32_t g_adjmask[512 * 16];   // adj bitmask: row i, word w = bits j=32w..32w+31

// ---------------------------------------------------------------------------
// helpers
// ---------------------------------------------------------------------------
// FMA-pipe exp (no MUFU). Valid for |x| < ~60; here |x| <= ~5.
__device__ __forceinline__ float fexp(float x) {
    float y = fmaf(x, 1.4426950408889634f, 12582912.0f);   // round-to-nearest int
    float f = fmaf(x, 1.4426950408889634f, -(y - 12582912.0f));
    float p = 1.3333558146e-3f;
    p = fmaf(p, f, 9.6181291076e-3f);
    p = fmaf(p, f, 5.5504108664e-2f);
    p = fmaf(p, f, 2.4022650695e-1f);
    p = fmaf(p, f, 6.9314718056e-1f);
    p = fmaf(p, f, 1.0f);
    int ni = __float_as_int(y) - 0x4B400000;
    return __int_as_float(__float_as_int(p) + (ni << 23));
}

__device__ __forceinline__ void mma_f16(float* d, const uint32_t* a, const uint32_t* b) {
    asm volatile(
        "mma.sync.aligned.m16n8k16.row.col.f32.f16.f16.f32 "
        "{%0,%1,%2,%3}, {%4,%5,%6,%7}, {%8,%9}, {%0,%1,%2,%3};"
        : "+f"(d[0]), "+f"(d[1]), "+f"(d[2]), "+f"(d[3])
        : "r"(a[0]), "r"(a[1]), "r"(a[2]), "r"(a[3]), "r"(b[0]), "r"(b[1]));
}

#define LDSM_X4(r, addr) \
    asm volatile("ldmatrix.sync.aligned.m8n8.x4.shared.b16 {%0,%1,%2,%3}, [%4];" \
        : "=r"((r)[0]), "=r"((r)[1]), "=r"((r)[2]), "=r"((r)[3]) : "r"(addr))

// ---------------------------------------------------------------------------
// Kernel 0: compress adj (512x512 int) -> bitmask (512x16 u32).
// ---------------------------------------------------------------------------
__global__ __launch_bounds__(256)
void gat_adjmask(const int* __restrict__ adj) {
    int gw = (blockIdx.x * 256 + threadIdx.x) >> 5;   // warp id 0..8191
    int lane = threadIdx.x & 31;
    int row = gw >> 4, word = gw & 15;
    int v = adj[row * 512 + word * 32 + lane];
    unsigned m = __ballot_sync(0xffffffffu, v > 0);
    if (lane == 0) g_adjmask[gw] = m;
}

// ---------------------------------------------------------------------------
// Kernel A: Wh = h @ W (fp32), fused es/ed dots; writes Wh TRANSPOSED as fp16:
// g_WhT[s][c][j]. es/ed from full-precision accumulators.
// ---------------------------------------------------------------------------
__global__ __launch_bounds__(256, 2)
void gat_wh_kernel(const float* __restrict__ h, const float* __restrict__ W,
                   const float* __restrict__ a) {
    __shared__ float Ws[32 * 132];
    __shared__ float hs[64 * 33];
    __shared__ float a_sh[256];

    int t = threadIdx.x;
    int rg = t >> 3;
    int cg = t & 7;
    long brow = (long)blockIdx.x * 64;
    int slice = blockIdx.x >> 3;
    int jloc = (blockIdx.x & 7) * 64 + rg;

    a_sh[t] = a[t];

    float acc0[16], acc1[16];
#pragma unroll
    for (int i = 0; i < 16; i++) { acc0[i] = 0.f; acc1[i] = 0.f; }

    for (int kt = 0; kt < 4; kt++) {
        __syncthreads();
        {
            const float4* Wg = (const float4*)(W + kt * 32 * 128);
            float4* Wd = (float4*)Ws;
#pragma unroll
            for (int m = 0; m < 4; m++) {
                int idx = t + m * 256;
                int r = idx >> 5, w = idx & 31;
                Wd[r * 33 + w] = Wg[r * 32 + w];
            }
        }
#pragma unroll
        for (int m = 0; m < 8; m++) {
            int idx = t + m * 256;
            int r = idx >> 5, k = idx & 31;
            hs[r * 33 + k] = h[(brow + r) * 128 + kt * 32 + k];
        }
        __syncthreads();

        const float4* Wv = (const float4*)Ws;
#pragma unroll 4
        for (int k = 0; k < 32; k++) {
            float hv0 = hs[rg * 33 + k];
            float hv1 = hs[(rg + 32) * 33 + k];
#pragma unroll
            for (int q = 0; q < 4; q++) {
                float4 w4 = Wv[k * 33 + cg + 8 * q];
                acc0[q * 4 + 0] += hv0 * w4.x; acc0[q * 4 + 1] += hv0 * w4.y;
                acc0[q * 4 + 2] += hv0 * w4.z; acc0[q * 4 + 3] += hv0 * w4.w;
                acc1[q * 4 + 0] += hv1 * w4.x; acc1[q * 4 + 1] += hv1 * w4.y;
                acc1[q * 4 + 2] += hv1 * w4.z; acc1[q * 4 + 3] += hv1 * w4.w;
            }
        }
    }

    __half* WhT = g_WhT + (long)slice * 128 * 512;
    float s0 = 0.f, s1 = 0.f, d0 = 0.f, d1 = 0.f;
#pragma unroll
    for (int q = 0; q < 4; q++) {
#pragma unroll
        for (int e = 0; e < 4; e++) {
            int c = 4 * cg + 32 * q + e;
            float v0 = acc0[q * 4 + e], v1 = acc1[q * 4 + e];
            WhT[(long)c * 512 + jloc]      = __float2half_rn(v0);
            WhT[(long)c * 512 + jloc + 32] = __float2half_rn(v1);
            float as = a_sh[c], ad = a_sh[128 + c];
            s0 += v0 * as; d0 += v0 * ad;
            s1 += v1 * as; d1 += v1 * ad;
        }
    }
#pragma unroll
    for (int o = 4; o >= 1; o >>= 1) {
        s0 += __shfl_xor_sync(0xffffffffu, s0, o);
        d0 += __shfl_xor_sync(0xffffffffu, d0, o);
        s1 += __shfl_xor_sync(0xffffffffu, s1, o);
        d1 += __shfl_xor_sync(0xffffffffu, d1, o);
    }
    if (cg == 0) {
        g_es[brow + rg] = s0;       g_ed[brow + rg] = d0;
        g_es[brow + rg + 32] = s1;  g_ed[brow + rg + 32] = d1;
    }
}

// ---------------------------------------------------------------------------
// Kernel B: D[128i x 128d] = P[128 x 512] @ Wh[512 x 128], mma m16n8k16 fp16.
// Double-buffered Ps/Bs; role-alternating warps; cp.async B staging; adj via
// bitmask (1 LDG.32 per thread per jt); fragments via ldmatrix.x4.
// ---------------------------------------------------------------------------
static constexpr int SPH = 68;                          // u32 (half2) stride
static constexpr int BUF = 128 * SPH;                   // u32 per buffer
static constexpr int SMEM_ATTN = (4 * BUF + 128) * 4;   // 139,776 B

__global__ __launch_bounds__(512, 1)
void gat_attn_mma(float* __restrict__ out) {
    extern __shared__ uint32_t smu[];
    uint32_t* Ps = smu;                 // 2 x (128 x 68)
    uint32_t* Bs = smu + 2 * BUF;       // 2 x (128 x 68)
    float* l_sh = (float*)(smu + 4 * BUF);

    int t = threadIdx.x;
    int w = t >> 5;
    int l = t & 31;
    int bt = blockIdx.x >> 2;
    int ibase = (blockIdx.x & 3) * 128;
    long rowbase = (long)bt * 512;

    if (t < 128) l_sh[t] = 0.f;

    // P-build mapping: thread t -> row t>>2, j quarter (t&3)*32
    int i_row = t >> 2;
    int jbase = (t & 3) * 32;
    int kkb = (t & 3) * 16;
    float es_i = g_es[rowbase + ibase + i_row];

    // MMA mapping: warp (wm = w>>2, wn = w&3)
    int wm = w >> 2, wn = w & 3;
    int gid = l >> 2, tig = l & 3;

    const __half* WhT = g_WhT + (long)bt * 128 * 512;

    uint32_t ps_addr, bs_addr;
    asm("{ .reg .u64 tt; cvta.to.shared.u64 tt, %1; cvt.u32.u64 %0, tt; }"
        : "=r"(ps_addr) : "l"((const void*)Ps));
    asm("{ .reg .u64 tt; cvta.to.shared.u64 tt, %1; cvt.u32.u64 %0, tt; }"
        : "=r"(bs_addr) : "l"((const void*)Bs));

    // ldmatrix lane address components.
    // A (x4 per mt): rows = rb + (l&7) + 8*((l>>3)&1), u32col = k0 + 4*(l>>4)
    uint32_t a_lane = (uint32_t)((wm * 32 + (l & 7) + 8 * ((l >> 3) & 1)) * SPH
                                 + 4 * (l >> 4)) * 4u;
    // B (x4 per nt-pair): rows = nb0 + (l&7) + 8*(l>>4), u32col = k0 + 4*((l>>3)&1)
    uint32_t b_lane = (uint32_t)((wn * 32 + (l & 7) + 8 * (l >> 4)) * SPH
                                 + 4 * ((l >> 3) & 1)) * 4u;

    float acc[2][4][4];
#pragma unroll
    for (int mt = 0; mt < 2; mt++)
#pragma unroll
        for (int nt = 0; nt < 4; nt++)
#pragma unroll
            for (int e = 0; e < 4; e++) acc[mt][nt][e] = 0.f;

    auto stage_B = [&](int jt, int buf) {
#pragma unroll
        for (int m = 0; m < 4; m++) {
            int idx = t + m * 512;
            int d = idx >> 4, ch = idx & 15;
            uint32_t dst = bs_addr + (uint32_t)(buf * BUF * 4 + d * SPH * 4 + ch * 16);
            const void* src = WhT + (long)d * 512 + jt * 128 + ch * 8;
            asm volatile("cp.async.ca.shared.global [%0], [%1], 16;" :: "r"(dst), "l"(src));
        }
        asm volatile("cp.async.commit_group;" ::: "memory");
    };

    auto build_P = [&](int jt, int buf) {
        uint32_t* Pb = Ps + buf * BUF;
        float lsum = 0.f;
        uint32_t mask = g_adjmask[(ibase + i_row) * 16 + jt * 4 + (t & 3)];
        const float4* edp = (const float4*)(g_ed + rowbase + jt * 128 + jbase);
#pragma unroll
        for (int c = 0; c < 8; c++) {
            float4 edv = __ldg(edp + c);
            float x, p0, p1, p2, p3;
            x = es_i + edv.x; x = fmaxf(x, ALPHA * x); p0 = (mask >> (4 * c))     & 1 ? fexp(x) : 0.f;
            x = es_i + edv.y; x = fmaxf(x, ALPHA * x); p1 = (mask >> (4 * c + 1)) & 1 ? fexp(x) : 0.f;
            x = es_i + edv.z; x = fmaxf(x, ALPHA * x); p2 = (mask >> (4 * c + 2)) & 1 ? fexp(x) : 0.f;
            x = es_i + edv.w; x = fmaxf(x, ALPHA * x); p3 = (mask >> (4 * c + 3)) & 1 ? fexp(x) : 0.f;
            lsum += p0 + p1 + p2 + p3;
            __half2 h01 = __float22half2_rn(make_float2(p0, p1));
            __half2 h23 = __float22half2_rn(make_float2(p2, p3));
            uint2 st;
            st.x = *(uint32_t*)&h01;
            st.y = *(uint32_t*)&h23;
            *(uint2*)&Pb[i_row * SPH + kkb + 2 * c] = st;
        }
        lsum += __shfl_xor_sync(0xffffffffu, lsum, 1);
        lsum += __shfl_xor_sync(0xffffffffu, lsum, 2);
        if ((t & 3) == 0) l_sh[i_row] += lsum;
    };

    auto do_mma = [&](int buf) {
        uint32_t pa = ps_addr + (uint32_t)(buf * BUF * 4) + a_lane;
        uint32_t ba = bs_addr + (uint32_t)(buf * BUF * 4) + b_lane;
        const uint32_t mt_step = 16 * SPH * 4;   // +16 rows
#pragma unroll
        for (int ks = 0; ks < 8; ks++) {
            uint32_t A0[4], A1[4], B0[4], B1[4];
            LDSM_X4(A0, pa);
            LDSM_X4(A1, pa + mt_step);
            LDSM_X4(B0, ba);
            LDSM_X4(B1, ba + mt_step);
            uint32_t* Af[2] = {A0, A1};
            uint32_t Bf[4][2] = {{B0[0], B0[1]}, {B0[2], B0[3]},
                                 {B1[0], B1[1]}, {B1[2], B1[3]}};
#pragma unroll
            for (int mt = 0; mt < 2; mt++)
#pragma unroll
                for (int nt = 0; nt < 4; nt++)
                    mma_f16(acc[mt][nt], Af[mt], Bf[nt]);
            pa += 32;   // k0 += 8 u32
            ba += 32;
        }
    };

    __syncthreads();   // l_sh init visible before first build_P

    // Prologue: stage Bs[0] + build Ps[0].
    stage_B(0, 0);
    build_P(0, 0);
    asm volatile("cp.async.wait_group 0;" ::: "memory");
    __syncthreads();

    for (int jt = 0; jt < 4; jt++) {
        int buf = jt & 1, nbuf = buf ^ 1;
        if (jt < 3) stage_B(jt + 1, nbuf);
        if (w & 1) {
            if (jt < 3) build_P(jt + 1, nbuf);
            do_mma(buf);
        } else {
            do_mma(buf);
            if (jt < 3) build_P(jt + 1, nbuf);
        }
        asm volatile("cp.async.wait_group 0;" ::: "memory");
        __syncthreads();
    }

    // Epilogue: out = acc / l.
#pragma unroll
    for (int mt = 0; mt < 2; mt++) {
        int rb = wm * 32 + mt * 16;
        float inv0 = 1.f / l_sh[rb + gid];
        float inv1 = 1.f / l_sh[rb + gid + 8];
        long row0 = rowbase + ibase + rb + gid;
        long row1 = row0 + 8;
#pragma unroll
        for (int nt = 0; nt < 4; nt++) {
            int col = wn * 32 + nt * 8 + 2 * tig;
            *(float2*)(out + row0 * 128 + col) =
                make_float2(acc[mt][nt][0] * inv0, acc[mt][nt][1] * inv0);
            *(float2*)(out + row1 * 128 + col) =
                make_float2(acc[mt][nt][2] * inv1, acc[mt][nt][3] * inv1);
        }
    }
}

extern "C" void kernel_launch(void* const* d_in, const int* in_sizes, int n_in,
                              void* d_out, int out_size) {
    const float* h   = (const float*)d_in[0];
    const int*   adj = (const int*)d_in[1];
    const float* W   = (const float*)d_in[2];
    const float* a   = (const float*)d_in[3];
    float* out = (float*)d_out;

    int BT = in_sizes[0] / (512 * 128);
    if (BT > 128) BT = 128;

    cudaFuncSetAttribute(gat_attn_mma,
                         cudaFuncAttributeMaxDynamicSharedMemorySize, SMEM_ATTN);

    gat_adjmask<<<1024, 256>>>(adj);
    gat_wh_kernel<<<BT * 8, 256>>>(h, W, a);
    gat_attn_mma<<<BT * 4, 512, SMEM_ATTN>>>(out);
}

// round 9
// speedup vs baseline: 2.9355x; 1.6510x over previous
#include <cuda_runtime.h>
#include <cuda_fp16.h>
#include <cstdint>

#define ALPHA 0.2f

// Scratch: max BT = 128 slices. g_Wh layout: [row(65536)][d(128)], fp16.
__device__ __half g_Wh[128 * 512 * 128];
__device__ float g_es[128 * 512];
__device__ float g_ed[128 * 512];
__device__ uint32_t g_adjmask[512 * 16];   // row i, word w = bits j=32w..32w+31

// ---------------------------------------------------------------------------
// helpers
// ---------------------------------------------------------------------------
// FMA-pipe exp (no MUFU). Valid for |x| < ~60; here |x| <= ~5.
__device__ __forceinline__ float fexp(float x) {
    float y = fmaf(x, 1.4426950408889634f, 12582912.0f);   // round-to-nearest int
    float f = fmaf(x, 1.4426950408889634f, -(y - 12582912.0f));
    float p = 1.3333558146e-3f;
    p = fmaf(p, f, 9.6181291076e-3f);
    p = fmaf(p, f, 5.5504108664e-2f);
    p = fmaf(p, f, 2.4022650695e-1f);
    p = fmaf(p, f, 6.9314718056e-1f);
    p = fmaf(p, f, 1.0f);
    int ni = __float_as_int(y) - 0x4B400000;
    return __int_as_float(__float_as_int(p) + (ni << 23));
}

__device__ __forceinline__ void mma_f16(float* d, const uint32_t* a, const uint32_t* b) {
    asm volatile(
        "mma.sync.aligned.m16n8k16.row.col.f32.f16.f16.f32 "
        "{%0,%1,%2,%3}, {%4,%5,%6,%7}, {%8,%9}, {%0,%1,%2,%3};"
        : "+f"(d[0]), "+f"(d[1]), "+f"(d[2]), "+f"(d[3])
        : "r"(a[0]), "r"(a[1]), "r"(a[2]), "r"(a[3]), "r"(b[0]), "r"(b[1]));
}

#define LDSM_X4(r, addr) \
    asm volatile("ldmatrix.sync.aligned.m8n8.x4.shared.b16 {%0,%1,%2,%3}, [%4];" \
        : "=r"((r)[0]), "=r"((r)[1]), "=r"((r)[2]), "=r"((r)[3]) : "r"(addr))

#define LDSM_X4_T(r, addr) \
    asm volatile("ldmatrix.sync.aligned.m8n8.x4.trans.shared.b16 {%0,%1,%2,%3}, [%4];" \
        : "=r"((r)[0]), "=r"((r)[1]), "=r"((r)[2]), "=r"((r)[3]) : "r"(addr))

static constexpr int SPH = 68;            // u32 (half2) row stride for MMA tiles
static constexpr int BUF = 128 * SPH;     // u32 per 128-row tile

// ---------------------------------------------------------------------------
// Kernel 0: compress adj (512x512 int) -> bitmask (512x16 u32).
// ---------------------------------------------------------------------------
__global__ __launch_bounds__(256)
void gat_adjmask(const int* __restrict__ adj) {
    int gw = (blockIdx.x * 256 + threadIdx.x) >> 5;
    int lane = threadIdx.x & 31;
    int row = gw >> 4, word = gw & 15;
    int v = adj[row * 512 + word * 32 + lane];
    unsigned m = __ballot_sync(0xffffffffu, v > 0);
    if (lane == 0) g_adjmask[gw] = m;
}

// ---------------------------------------------------------------------------
// Kernel A (tensor-core): Wh = h @ W via m16n8k16 fp16, K=128 single-shot.
// Per CTA: 128 rows x 128 cols. hs[row][k], Ws[k][d] (B frags via ldmatrix.trans).
// Epilogue: g_Wh[row][d] (half2 direct STG) + es/ed dots (fp32 acc + smem atomics).
// ---------------------------------------------------------------------------
static constexpr int SMEM_WH = (2 * BUF + 512) * 4;   // 71,680 B

__global__ __launch_bounds__(512, 1)
void gat_wh_mma(const float* __restrict__ h, const float* __restrict__ W,
                const float* __restrict__ a) {
    extern __shared__ uint32_t smu[];
    uint32_t* hs = smu;                  // [row 128][k half2 34] stride 68
    uint32_t* Ws = smu + BUF;            // [k 128][d half2 34] stride 68
    float* a_sh  = (float*)(smu + 2 * BUF);
    float* es_sm = a_sh + 256;
    float* ed_sm = es_sm + 128;

    int t = threadIdx.x, w = t >> 5, l = t & 31;
    long brow = (long)blockIdx.x * 128;

    if (t < 256) a_sh[t] = a[t];
    if (t < 128) { es_sm[t] = 0.f; ed_sm[t] = 0.f; }

    // Stage h tile (fp32 -> fp16) and W (fp32 -> fp16, natural [k][d]).
    {
        const float4* hg = (const float4*)(h + brow * 128);
        const float4* Wg = (const float4*)W;
#pragma unroll
        for (int m = 0; m < 8; m++) {
            int idx = t + m * 512;               // 0..4095
            int r = idx >> 5, c4 = idx & 31;
            float4 v = hg[idx];
            uint2 st;
            __half2 p0 = __floats2half2_rn(v.x, v.y);
            __half2 p1 = __floats2half2_rn(v.z, v.w);
            st.x = *(uint32_t*)&p0; st.y = *(uint32_t*)&p1;
            *(uint2*)&hs[r * SPH + 2 * c4] = st;

            float4 wv = Wg[idx];
            __half2 q0 = __floats2half2_rn(wv.x, wv.y);
            __half2 q1 = __floats2half2_rn(wv.z, wv.w);
            st.x = *(uint32_t*)&q0; st.y = *(uint32_t*)&q1;
            *(uint2*)&Ws[r * SPH + 2 * c4] = st;
        }
    }
    __syncthreads();

    int wm = w >> 2, wn = w & 3;
    int gid = l >> 2, tig = l & 3;

    uint32_t hs_addr, ws_addr;
    asm("{ .reg .u64 tt; cvta.to.shared.u64 tt, %1; cvt.u32.u64 %0, tt; }"
        : "=r"(hs_addr) : "l"((const void*)hs));
    asm("{ .reg .u64 tt; cvta.to.shared.u64 tt, %1; cvt.u32.u64 %0, tt; }"
        : "=r"(ws_addr) : "l"((const void*)Ws));

    uint32_t a_lane = (uint32_t)((wm * 32 + (l & 7) + 8 * ((l >> 3) & 1)) * SPH
                                 + 4 * (l >> 4)) * 4u;
    // trans B: rows = k, cols = d halves
    uint32_t b_lane = (uint32_t)(((l & 7) + 8 * ((l >> 3) & 1)) * SPH) * 4u
                    + (uint32_t)(wn * 32 + 8 * (l >> 4)) * 2u;

    float acc[2][4][4];
#pragma unroll
    for (int mt = 0; mt < 2; mt++)
#pragma unroll
        for (int nt = 0; nt < 4; nt++)
#pragma unroll
            for (int e = 0; e < 4; e++) acc[mt][nt][e] = 0.f;

    uint32_t pa = hs_addr + a_lane;
    uint32_t ba = ws_addr + b_lane;
    const uint32_t mt_step = 16 * SPH * 4;
#pragma unroll
    for (int ks = 0; ks < 8; ks++) {
        uint32_t A0[4], A1[4], B0[4], B1[4];
        LDSM_X4(A0, pa);
        LDSM_X4(A1, pa + mt_step);
        LDSM_X4_T(B0, ba);
        LDSM_X4_T(B1, ba + 32);          // +16 d halves
        uint32_t* Af[2] = {A0, A1};
        uint32_t Bf[4][2] = {{B0[0], B0[1]}, {B0[2], B0[3]},
                             {B1[0], B1[1]}, {B1[2], B1[3]}};
#pragma unroll
        for (int mt = 0; mt < 2; mt++)
#pragma unroll
            for (int nt = 0; nt < 4; nt++)
                mma_f16(acc[mt][nt], Af[mt], Bf[nt]);
        pa += 32;                        // k += 16 halves
        ba += 16 * SPH * 4;              // k rows += 16
    }

    // Epilogue: g_Wh[row][d] half2 stores + es/ed dots.
#pragma unroll
    for (int mt = 0; mt < 2; mt++) {
        int r0 = wm * 32 + mt * 16 + gid;
        int r1 = r0 + 8;
        float s0 = 0.f, d0 = 0.f, s1 = 0.f, d1 = 0.f;
#pragma unroll
        for (int nt = 0; nt < 4; nt++) {
            int col = wn * 32 + nt * 8 + 2 * tig;
            __half2 v0 = __floats2half2_rn(acc[mt][nt][0], acc[mt][nt][1]);
            __half2 v1 = __floats2half2_rn(acc[mt][nt][2], acc[mt][nt][3]);
            *(__half2*)(g_Wh + (brow + r0) * 128 + col) = v0;
            *(__half2*)(g_Wh + (brow + r1) * 128 + col) = v1;
            s0 += acc[mt][nt][0] * a_sh[col] + acc[mt][nt][1] * a_sh[col + 1];
            d0 += acc[mt][nt][0] * a_sh[128 + col] + acc[mt][nt][1] * a_sh[128 + col + 1];
            s1 += acc[mt][nt][2] * a_sh[col] + acc[mt][nt][3] * a_sh[col + 1];
            d1 += acc[mt][nt][2] * a_sh[128 + col] + acc[mt][nt][3] * a_sh[128 + col + 1];
        }
#pragma unroll
        for (int o = 1; o <= 2; o <<= 1) {
            s0 += __shfl_xor_sync(0xffffffffu, s0, o);
            d0 += __shfl_xor_sync(0xffffffffu, d0, o);
            s1 += __shfl_xor_sync(0xffffffffu, s1, o);
            d1 += __shfl_xor_sync(0xffffffffu, d1, o);
        }
        if (tig == 0) {
            atomicAdd(es_sm + r0, s0); atomicAdd(ed_sm + r0, d0);
            atomicAdd(es_sm + r1, s1); atomicAdd(ed_sm + r1, d1);
        }
    }
    __syncthreads();
    if (t < 128) {
        g_es[brow + t] = es_sm[t];
        g_ed[brow + t] = ed_sm[t];
    }
}

// ---------------------------------------------------------------------------
// Kernel B: D[128i x 128d] = P[128 x 512] @ Wh[512 x 128], mma m16n8k16 fp16.
// Double-buffered Ps/Bs; role-alternating warps; cp.async B staging from
// g_Wh[j][d]; B fragments via ldmatrix.trans; adj via bitmask.
// ---------------------------------------------------------------------------
static constexpr int SMEM_ATTN = (4 * BUF + 128) * 4;   // 139,776 B

__global__ __launch_bounds__(512, 1)
void gat_attn_mma(float* __restrict__ out) {
    extern __shared__ uint32_t smu[];
    uint32_t* Ps = smu;                 // 2 x [i 128][k half2 34] stride 68
    uint32_t* Bs = smu + 2 * BUF;       // 2 x [k 128][d half2 34] stride 68
    float* l_sh = (float*)(smu + 4 * BUF);

    int t = threadIdx.x;
    int w = t >> 5;
    int l = t & 31;
    int bt = blockIdx.x >> 2;
    int ibase = (blockIdx.x & 3) * 128;
    long rowbase = (long)bt * 512;

    if (t < 128) l_sh[t] = 0.f;

    int i_row = t >> 2;
    int jbase = (t & 3) * 32;
    int kkb = (t & 3) * 16;
    float es_i = g_es[rowbase + ibase + i_row];

    int wm = w >> 2, wn = w & 3;
    int gid = l >> 2, tig = l & 3;

    const __half* Whb = g_Wh + rowbase * 128;

    uint32_t ps_addr, bs_addr;
    asm("{ .reg .u64 tt; cvta.to.shared.u64 tt, %1; cvt.u32.u64 %0, tt; }"
        : "=r"(ps_addr) : "l"((const void*)Ps));
    asm("{ .reg .u64 tt; cvta.to.shared.u64 tt, %1; cvt.u32.u64 %0, tt; }"
        : "=r"(bs_addr) : "l"((const void*)Bs));

    uint32_t a_lane = (uint32_t)((wm * 32 + (l & 7) + 8 * ((l >> 3) & 1)) * SPH
                                 + 4 * (l >> 4)) * 4u;
    uint32_t b_lane = (uint32_t)(((l & 7) + 8 * ((l >> 3) & 1)) * SPH) * 4u
                    + (uint32_t)(wn * 32 + 8 * (l >> 4)) * 2u;

    float acc[2][4][4];
#pragma unroll
    for (int mt = 0; mt < 2; mt++)
#pragma unroll
        for (int nt = 0; nt < 4; nt++)
#pragma unroll
            for (int e = 0; e < 4; e++) acc[mt][nt][e] = 0.f;

    auto stage_B = [&](int jt, int buf) {
#pragma unroll
        for (int m = 0; m < 4; m++) {
            int idx = t + m * 512;
            int j = idx >> 4, ch = idx & 15;
            uint32_t dst = bs_addr + (uint32_t)(buf * BUF * 4 + j * SPH * 4 + ch * 16);
            const void* src = Whb + (long)(jt * 128 + j) * 128 + ch * 8;
            asm volatile("cp.async.ca.shared.global [%0], [%1], 16;" :: "r"(dst), "l"(src));
        }
        asm volatile("cp.async.commit_group;" ::: "memory");
    };

    auto build_P = [&](int jt, int buf) {
        uint32_t* Pb = Ps + buf * BUF;
        float lsum = 0.f;
        uint32_t mask = g_adjmask[(ibase + i_row) * 16 + jt * 4 + (t & 3)];
        const float4* edp = (const float4*)(g_ed + rowbase + jt * 128 + jbase);
#pragma unroll
        for (int c = 0; c < 8; c++) {
            float4 edv = __ldg(edp + c);
            float x, p0, p1, p2, p3;
            x = es_i + edv.x; x = fmaxf(x, ALPHA * x); p0 = (mask >> (4 * c))     & 1 ? fexp(x) : 0.f;
            x = es_i + edv.y; x = fmaxf(x, ALPHA * x); p1 = (mask >> (4 * c + 1)) & 1 ? fexp(x) : 0.f;
            x = es_i + edv.z; x = fmaxf(x, ALPHA * x); p2 = (mask >> (4 * c + 2)) & 1 ? fexp(x) : 0.f;
            x = es_i + edv.w; x = fmaxf(x, ALPHA * x); p3 = (mask >> (4 * c + 3)) & 1 ? fexp(x) : 0.f;
            lsum += p0 + p1 + p2 + p3;
            __half2 h01 = __float22half2_rn(make_float2(p0, p1));
            __half2 h23 = __float22half2_rn(make_float2(p2, p3));
            uint2 st;
            st.x = *(uint32_t*)&h01;
            st.y = *(uint32_t*)&h23;
            *(uint2*)&Pb[i_row * SPH + kkb + 2 * c] = st;
        }
        lsum += __shfl_xor_sync(0xffffffffu, lsum, 1);
        lsum += __shfl_xor_sync(0xffffffffu, lsum, 2);
        if ((t & 3) == 0) l_sh[i_row] += lsum;
    };

    auto do_mma = [&](int buf) {
        uint32_t pa = ps_addr + (uint32_t)(buf * BUF * 4) + a_lane;
        uint32_t ba = bs_addr + (uint32_t)(buf * BUF * 4) + b_lane;
        const uint32_t mt_step = 16 * SPH * 4;
#pragma unroll
        for (int ks = 0; ks < 8; ks++) {
            uint32_t A0[4], A1[4], B0[4], B1[4];
            LDSM_X4(A0, pa);
            LDSM_X4(A1, pa + mt_step);
            LDSM_X4_T(B0, ba);
            LDSM_X4_T(B1, ba + 32);
            uint32_t* Af[2] = {A0, A1};
            uint32_t Bf[4][2] = {{B0[0], B0[1]}, {B0[2], B0[3]},
                                 {B1[0], B1[1]}, {B1[2], B1[3]}};
#pragma unroll
            for (int mt = 0; mt < 2; mt++)
#pragma unroll
                for (int nt = 0; nt < 4; nt++)
                    mma_f16(acc[mt][nt], Af[mt], Bf[nt]);
            pa += 32;               // k += 16 halves
            ba += 16 * SPH * 4;     // k rows += 16
        }
    };

    __syncthreads();   // l_sh init visible before first build_P

    stage_B(0, 0);
    build_P(0, 0);
    asm volatile("cp.async.wait_group 0;" ::: "memory");
    __syncthreads();

    for (int jt = 0; jt < 4; jt++) {
        int buf = jt & 1, nbuf = buf ^ 1;
        if (jt < 3) stage_B(jt + 1, nbuf);
        if (w & 1) {
            if (jt < 3) build_P(jt + 1, nbuf);
            do_mma(buf);
        } else {
            do_mma(buf);
            if (jt < 3) build_P(jt + 1, nbuf);
        }
        asm volatile("cp.async.wait_group 0;" ::: "memory");
        __syncthreads();
    }

    // Epilogue: out = acc / l.
#pragma unroll
    for (int mt = 0; mt < 2; mt++) {
        int rb = wm * 32 + mt * 16;
        float inv0 = 1.f / l_sh[rb + gid];
        float inv1 = 1.f / l_sh[rb + gid + 8];
        long row0 = rowbase + ibase + rb + gid;
        long row1 = row0 + 8;
#pragma unroll
        for (int nt = 0; nt < 4; nt++) {
            int col = wn * 32 + nt * 8 + 2 * tig;
            *(float2*)(out + row0 * 128 + col) =
                make_float2(acc[mt][nt][0] * inv0, acc[mt][nt][1] * inv0);
            *(float2*)(out + row1 * 128 + col) =
                make_float2(acc[mt][nt][2] * inv1, acc[mt][nt][3] * inv1);
        }
    }
}

extern "C" void kernel_launch(void* const* d_in, const int* in_sizes, int n_in,
                              void* d_out, int out_size) {
    const float* h   = (const float*)d_in[0];
    const int*   adj = (const int*)d_in[1];
    const float* W   = (const float*)d_in[2];
    const float* a   = (const float*)d_in[3];
    float* out = (float*)d_out;

    int BT = in_sizes[0] / (512 * 128);
    if (BT > 128) BT = 128;

    cudaFuncSetAttribute(gat_wh_mma,
                         cudaFuncAttributeMaxDynamicSharedMemorySize, SMEM_WH);
    cudaFuncSetAttribute(gat_attn_mma,
                         cudaFuncAttributeMaxDynamicSharedMemorySize, SMEM_ATTN);

    gat_adjmask<<<1024, 256>>>(adj);
    gat_wh_mma<<<BT * 4, 512, SMEM_WH>>>(h, W, a);
    gat_attn_mma<<<BT * 4, 512, SMEM_ATTN>>>(out);
}

// round 10
// speedup vs baseline: 3.5646x; 1.2143x over previous
#include <cuda_runtime.h>
#include <cuda_fp16.h>
#include <cstdint>

#define ALPHA 0.2f

// Scratch: max BT = 128 slices. g_Wh layout: [row(65536)][d(128)], fp16.
__device__ __half g_Wh[128 * 512 * 128];
__device__ float g_es[128 * 512];
__device__ float g_ed[128 * 512];
__device__ uint32_t g_adjmask[512 * 16];   // row i, word w = bits j=32w..32w+31

// ---------------------------------------------------------------------------
// helpers
// ---------------------------------------------------------------------------
__device__ __forceinline__ void mma_f16(float* d, const uint32_t* a, const uint32_t* b) {
    asm volatile(
        "mma.sync.aligned.m16n8k16.row.col.f32.f16.f16.f32 "
        "{%0,%1,%2,%3}, {%4,%5,%6,%7}, {%8,%9}, {%0,%1,%2,%3};"
        : "+f"(d[0]), "+f"(d[1]), "+f"(d[2]), "+f"(d[3])
        : "r"(a[0]), "r"(a[1]), "r"(a[2]), "r"(a[3]), "r"(b[0]), "r"(b[1]));
}

#define LDSM_X4(r, addr) \
    asm volatile("ldmatrix.sync.aligned.m8n8.x4.shared.b16 {%0,%1,%2,%3}, [%4];" \
        : "=r"((r)[0]), "=r"((r)[1]), "=r"((r)[2]), "=r"((r)[3]) : "r"(addr))

#define LDSM_X4_T(r, addr) \
    asm volatile("ldmatrix.sync.aligned.m8n8.x4.trans.shared.b16 {%0,%1,%2,%3}, [%4];" \
        : "=r"((r)[0]), "=r"((r)[1]), "=r"((r)[2]), "=r"((r)[3]) : "r"(addr))

static constexpr int SPH = 68;            // u32 (half2) row stride for MMA tiles
static constexpr int BUF = 128 * SPH;     // u32 per 128-row tile

// ---------------------------------------------------------------------------
// Kernel 0: compress adj (512x512 int) -> bitmask (512x16 u32).
// ---------------------------------------------------------------------------
__global__ __launch_bounds__(256)
void gat_adjmask(const int* __restrict__ adj) {
    int gw = (blockIdx.x * 256 + threadIdx.x) >> 5;
    int lane = threadIdx.x & 31;
    int row = gw >> 4, word = gw & 15;
    int v = adj[row * 512 + word * 32 + lane];
    unsigned m = __ballot_sync(0xffffffffu, v > 0);
    if (lane == 0) g_adjmask[gw] = m;
}

// ---------------------------------------------------------------------------
// Kernel A (tensor-core): Wh = h @ W via m16n8k16 fp16, K=128 single-shot.
// ---------------------------------------------------------------------------
static constexpr int SMEM_WH = (2 * BUF + 512) * 4;   // 71,680 B

__global__ __launch_bounds__(512, 1)
void gat_wh_mma(const float* __restrict__ h, const float* __restrict__ W,
                const float* __restrict__ a) {
    extern __shared__ uint32_t smu[];
    uint32_t* hs = smu;                  // [row 128][k half2 34] stride 68
    uint32_t* Ws = smu + BUF;            // [k 128][d half2 34] stride 68
    float* a_sh  = (float*)(smu + 2 * BUF);
    float* es_sm = a_sh + 256;
    float* ed_sm = es_sm + 128;

    int t = threadIdx.x, w = t >> 5, l = t & 31;
    long brow = (long)blockIdx.x * 128;

    if (t < 256) a_sh[t] = a[t];
    if (t < 128) { es_sm[t] = 0.f; ed_sm[t] = 0.f; }

    {
        const float4* hg = (const float4*)(h + brow * 128);
        const float4* Wg = (const float4*)W;
#pragma unroll
        for (int m = 0; m < 8; m++) {
            int idx = t + m * 512;               // 0..4095
            int r = idx >> 5, c4 = idx & 31;
            float4 v = hg[idx];
            uint2 st;
            __half2 p0 = __floats2half2_rn(v.x, v.y);
            __half2 p1 = __floats2half2_rn(v.z, v.w);
            st.x = *(uint32_t*)&p0; st.y = *(uint32_t*)&p1;
            *(uint2*)&hs[r * SPH + 2 * c4] = st;

            float4 wv = Wg[idx];
            __half2 q0 = __floats2half2_rn(wv.x, wv.y);
            __half2 q1 = __floats2half2_rn(wv.z, wv.w);
            st.x = *(uint32_t*)&q0; st.y = *(uint32_t*)&q1;
            *(uint2*)&Ws[r * SPH + 2 * c4] = st;
        }
    }
    __syncthreads();

    int wm = w >> 2, wn = w & 3;
    int gid = l >> 2, tig = l & 3;

    uint32_t hs_addr, ws_addr;
    asm("{ .reg .u64 tt; cvta.to.shared.u64 tt, %1; cvt.u32.u64 %0, tt; }"
        : "=r"(hs_addr) : "l"((const void*)hs));
    asm("{ .reg .u64 tt; cvta.to.shared.u64 tt, %1; cvt.u32.u64 %0, tt; }"
        : "=r"(ws_addr) : "l"((const void*)Ws));

    uint32_t a_lane = (uint32_t)((wm * 32 + (l & 7) + 8 * ((l >> 3) & 1)) * SPH
                                 + 4 * (l >> 4)) * 4u;
    uint32_t b_lane = (uint32_t)(((l & 7) + 8 * ((l >> 3) & 1)) * SPH) * 4u
                    + (uint32_t)(wn * 32 + 8 * (l >> 4)) * 2u;

    float acc[2][4][4];
#pragma unroll
    for (int mt = 0; mt < 2; mt++)
#pragma unroll
        for (int nt = 0; nt < 4; nt++)
#pragma unroll
            for (int e = 0; e < 4; e++) acc[mt][nt][e] = 0.f;

    uint32_t pa = hs_addr + a_lane;
    uint32_t ba = ws_addr + b_lane;
    const uint32_t mt_step = 16 * SPH * 4;
#pragma unroll
    for (int ks = 0; ks < 8; ks++) {
        uint32_t A0[4], A1[4], B0[4], B1[4];
        LDSM_X4(A0, pa);
        LDSM_X4(A1, pa + mt_step);
        LDSM_X4_T(B0, ba);
        LDSM_X4_T(B1, ba + 32);          // +16 d halves
        uint32_t* Af[2] = {A0, A1};
        uint32_t Bf[4][2] = {{B0[0], B0[1]}, {B0[2], B0[3]},
                             {B1[0], B1[1]}, {B1[2], B1[3]}};
#pragma unroll
        for (int mt = 0; mt < 2; mt++)
#pragma unroll
            for (int nt = 0; nt < 4; nt++)
                mma_f16(acc[mt][nt], Af[mt], Bf[nt]);
        pa += 32;                        // k += 16 halves
        ba += 16 * SPH * 4;              // k rows += 16
    }

#pragma unroll
    for (int mt = 0; mt < 2; mt++) {
        int r0 = wm * 32 + mt * 16 + gid;
        int r1 = r0 + 8;
        float s0 = 0.f, d0 = 0.f, s1 = 0.f, d1 = 0.f;
#pragma unroll
        for (int nt = 0; nt < 4; nt++) {
            int col = wn * 32 + nt * 8 + 2 * tig;
            __half2 v0 = __floats2half2_rn(acc[mt][nt][0], acc[mt][nt][1]);
            __half2 v1 = __floats2half2_rn(acc[mt][nt][2], acc[mt][nt][3]);
            *(__half2*)(g_Wh + (brow + r0) * 128 + col) = v0;
            *(__half2*)(g_Wh + (brow + r1) * 128 + col) = v1;
            s0 += acc[mt][nt][0] * a_sh[col] + acc[mt][nt][1] * a_sh[col + 1];
            d0 += acc[mt][nt][0] * a_sh[128 + col] + acc[mt][nt][1] * a_sh[128 + col + 1];
            s1 += acc[mt][nt][2] * a_sh[col] + acc[mt][nt][3] * a_sh[col + 1];
            d1 += acc[mt][nt][2] * a_sh[128 + col] + acc[mt][nt][3] * a_sh[128 + col + 1];
        }
#pragma unroll
        for (int o = 1; o <= 2; o <<= 1) {
            s0 += __shfl_xor_sync(0xffffffffu, s0, o);
            d0 += __shfl_xor_sync(0xffffffffu, d0, o);
            s1 += __shfl_xor_sync(0xffffffffu, s1, o);
            d1 += __shfl_xor_sync(0xffffffffu, d1, o);
        }
        if (tig == 0) {
            atomicAdd(es_sm + r0, s0); atomicAdd(ed_sm + r0, d0);
            atomicAdd(es_sm + r1, s1); atomicAdd(ed_sm + r1, d1);
        }
    }
    __syncthreads();
    if (t < 128) {
        g_es[brow + t] = es_sm[t];
        g_ed[brow + t] = ed_sm[t];
    }
}

// ---------------------------------------------------------------------------
// Kernel B: D[128i x 128d] = P[128 x 512] @ Wh[512 x 128], mma m16n8k16 fp16.
// Double-buffered Ps/Bs; role-alternating warps; cp.async B staging; adj via
// bitmask; exp via MUFU (__expf) to offload the FMA pipe.
// ---------------------------------------------------------------------------
static constexpr int SMEM_ATTN = (4 * BUF + 128) * 4;   // 139,776 B

__global__ __launch_bounds__(512, 1)
void gat_attn_mma(float* __restrict__ out) {
    extern __shared__ uint32_t smu[];
    uint32_t* Ps = smu;                 // 2 x [i 128][k half2 34] stride 68
    uint32_t* Bs = smu + 2 * BUF;       // 2 x [k 128][d half2 34] stride 68
    float* l_sh = (float*)(smu + 4 * BUF);

    int t = threadIdx.x;
    int w = t >> 5;
    int l = t & 31;
    int bt = blockIdx.x >> 2;
    int ibase = (blockIdx.x & 3) * 128;
    long rowbase = (long)bt * 512;

    if (t < 128) l_sh[t] = 0.f;

    int i_row = t >> 2;
    int jbase = (t & 3) * 32;
    int kkb = (t & 3) * 16;
    float es_i = g_es[rowbase + ibase + i_row];

    int wm = w >> 2, wn = w & 3;
    int gid = l >> 2, tig = l & 3;

    const __half* Whb = g_Wh + rowbase * 128;

    uint32_t ps_addr, bs_addr;
    asm("{ .reg .u64 tt; cvta.to.shared.u64 tt, %1; cvt.u32.u64 %0, tt; }"
        : "=r"(ps_addr) : "l"((const void*)Ps));
    asm("{ .reg .u64 tt; cvta.to.shared.u64 tt, %1; cvt.u32.u64 %0, tt; }"
        : "=r"(bs_addr) : "l"((const void*)Bs));

    uint32_t a_lane = (uint32_t)((wm * 32 + (l & 7) + 8 * ((l >> 3) & 1)) * SPH
                                 + 4 * (l >> 4)) * 4u;
    uint32_t b_lane = (uint32_t)(((l & 7) + 8 * ((l >> 3) & 1)) * SPH) * 4u
                    + (uint32_t)(wn * 32 + 8 * (l >> 4)) * 2u;

    float acc[2][4][4];
#pragma unroll
    for (int mt = 0; mt < 2; mt++)
#pragma unroll
        for (int nt = 0; nt < 4; nt++)
#pragma unroll
            for (int e = 0; e < 4; e++) acc[mt][nt][e] = 0.f;

    auto stage_B = [&](int jt, int buf) {
#pragma unroll
        for (int m = 0; m < 4; m++) {
            int idx = t + m * 512;
            int j = idx >> 4, ch = idx & 15;
            uint32_t dst = bs_addr + (uint32_t)(buf * BUF * 4 + j * SPH * 4 + ch * 16);
            const void* src = Whb + (long)(jt * 128 + j) * 128 + ch * 8;
            asm volatile("cp.async.ca.shared.global [%0], [%1], 16;" :: "r"(dst), "l"(src));
        }
        asm volatile("cp.async.commit_group;" ::: "memory");
    };

    auto build_P = [&](int jt, int buf) {
        uint32_t* Pb = Ps + buf * BUF;
        float lsum = 0.f;
        uint32_t mask = g_adjmask[(ibase + i_row) * 16 + jt * 4 + (t & 3)];
        const float4* edp = (const float4*)(g_ed + rowbase + jt * 128 + jbase);
#pragma unroll
        for (int c = 0; c < 8; c++) {
            float4 edv = __ldg(edp + c);
            float x, p0, p1, p2, p3;
            x = es_i + edv.x; x = fmaxf(x, ALPHA * x); p0 = (mask >> (4 * c))     & 1 ? __expf(x) : 0.f;
            x = es_i + edv.y; x = fmaxf(x, ALPHA * x); p1 = (mask >> (4 * c + 1)) & 1 ? __expf(x) : 0.f;
            x = es_i + edv.z; x = fmaxf(x, ALPHA * x); p2 = (mask >> (4 * c + 2)) & 1 ? __expf(x) : 0.f;
            x = es_i + edv.w; x = fmaxf(x, ALPHA * x); p3 = (mask >> (4 * c + 3)) & 1 ? __expf(x) : 0.f;
            lsum += p0 + p1 + p2 + p3;
            __half2 h01 = __float22half2_rn(make_float2(p0, p1));
            __half2 h23 = __float22half2_rn(make_float2(p2, p3));
            uint2 st;
            st.x = *(uint32_t*)&h01;
            st.y = *(uint32_t*)&h23;
            *(uint2*)&Pb[i_row * SPH + kkb + 2 * c] = st;
        }
        lsum += __shfl_xor_sync(0xffffffffu, lsum, 1);
        lsum += __shfl_xor_sync(0xffffffffu, lsum, 2);
        if ((t & 3) == 0) l_sh[i_row] += lsum;
    };

    auto do_mma = [&](int buf) {
        uint32_t pa = ps_addr + (uint32_t)(buf * BUF * 4) + a_lane;
        uint32_t ba = bs_addr + (uint32_t)(buf * BUF * 4) + b_lane;
        const uint32_t mt_step = 16 * SPH * 4;
#pragma unroll
        for (int ks = 0; ks < 8; ks++) {
            uint32_t A0[4], A1[4], B0[4], B1[4];
            LDSM_X4(A0, pa);
            LDSM_X4(A1, pa + mt_step);
            LDSM_X4_T(B0, ba);
            LDSM_X4_T(B1, ba + 32);
            uint32_t* Af[2] = {A0, A1};
            uint32_t Bf[4][2] = {{B0[0], B0[1]}, {B0[2], B0[3]},
                                 {B1[0], B1[1]}, {B1[2], B1[3]}};
#pragma unroll
            for (int mt = 0; mt < 2; mt++)
#pragma unroll
                for (int nt = 0; nt < 4; nt++)
                    mma_f16(acc[mt][nt], Af[mt], Bf[nt]);
            pa += 32;               // k += 16 halves
            ba += 16 * SPH * 4;     // k rows += 16
        }
    };

    __syncthreads();   // l_sh init visible before first build_P

    stage_B(0, 0);
    build_P(0, 0);
    asm volatile("cp.async.wait_group 0;" ::: "memory");
    __syncthreads();

    for (int jt = 0; jt < 4; jt++) {
        int buf = jt & 1, nbuf = buf ^ 1;
        if (jt < 3) stage_B(jt + 1, nbuf);
        if (w & 1) {
            if (jt < 3) build_P(jt + 1, nbuf);
            do_mma(buf);
        } else {
            do_mma(buf);
            if (jt < 3) build_P(jt + 1, nbuf);
        }
        asm volatile("cp.async.wait_group 0;" ::: "memory");
        __syncthreads();
    }

    // Epilogue: out = acc / l.
#pragma unroll
    for (int mt = 0; mt < 2; mt++) {
        int rb = wm * 32 + mt * 16;
        float inv0 = 1.f / l_sh[rb + gid];
        float inv1 = 1.f / l_sh[rb + gid + 8];
        long row0 = rowbase + ibase + rb + gid;
        long row1 = row0 + 8;
#pragma unroll
        for (int nt = 0; nt < 4; nt++) {
            int col = wn * 32 + nt * 8 + 2 * tig;
            *(float2*)(out + row0 * 128 + col) =
                make_float2(acc[mt][nt][0] * inv0, acc[mt][nt][1] * inv0);
            *(float2*)(out + row1 * 128 + col) =
                make_float2(acc[mt][nt][2] * inv1, acc[mt][nt][3] * inv1);
        }
    }
}

extern "C" void kernel_launch(void* const* d_in, const int* in_sizes, int n_in,
                              void* d_out, int out_size) {
    const float* h   = (const float*)d_in[0];
    const int*   adj = (const int*)d_in[1];
    const float* W   = (const float*)d_in[2];
    const float* a   = (const float*)d_in[3];
    float* out = (float*)d_out;

    int BT = in_sizes[0] / (512 * 128);
    if (BT > 128) BT = 128;

    cudaFuncSetAttribute(gat_wh_mma,
                         cudaFuncAttributeMaxDynamicSharedMemorySize, SMEM_WH);
    cudaFuncSetAttribute(gat_attn_mma,
                         cudaFuncAttributeMaxDynamicSharedMemorySize, SMEM_ATTN);

    gat_adjmask<<<1024, 256>>>(adj);
    gat_wh_mma<<<BT * 4, 512, SMEM_WH>>>(h, W, a);
    gat_attn_mma<<<BT * 4, 512, SMEM_ATTN>>>(out);
}

// round 11
// speedup vs baseline: 3.8754x; 1.0872x over previous
#include <cuda_runtime.h>
#include <cuda_fp16.h>
#include <cstdint>

#define ALPHA 0.2f

// Scratch: max BT = 128 slices. g_Wh layout: [row(65536)][d(128)], fp16.
__device__ __half g_Wh[128 * 512 * 128];
__device__ float g_es[128 * 512];
__device__ float g_ed[128 * 512];
__device__ uint32_t g_adjmask[512 * 16];   // row i, word w = bits j=32w..32w+31

// ---------------------------------------------------------------------------
// helpers
// ---------------------------------------------------------------------------
__device__ __forceinline__ void mma_f16(float* d, const uint32_t* a, const uint32_t* b) {
    asm volatile(
        "mma.sync.aligned.m16n8k16.row.col.f32.f16.f16.f32 "
        "{%0,%1,%2,%3}, {%4,%5,%6,%7}, {%8,%9}, {%0,%1,%2,%3};"
        : "+f"(d[0]), "+f"(d[1]), "+f"(d[2]), "+f"(d[3])
        : "r"(a[0]), "r"(a[1]), "r"(a[2]), "r"(a[3]), "r"(b[0]), "r"(b[1]));
}

#define LDSM_X4(r, addr) \
    asm volatile("ldmatrix.sync.aligned.m8n8.x4.shared.b16 {%0,%1,%2,%3}, [%4];" \
        : "=r"((r)[0]), "=r"((r)[1]), "=r"((r)[2]), "=r"((r)[3]) : "r"(addr))

#define LDSM_X4_T(r, addr) \
    asm volatile("ldmatrix.sync.aligned.m8n8.x4.trans.shared.b16 {%0,%1,%2,%3}, [%4];" \
        : "=r"((r)[0]), "=r"((r)[1]), "=r"((r)[2]), "=r"((r)[3]) : "r"(addr))

static constexpr int SPH = 68;            // u32 (half2) row stride for MMA tiles
static constexpr int BUF = 128 * SPH;     // u32 per 128-row tile
static constexpr int BUFP = 64 * SPH;     // u32 per 64-row tile

// ---------------------------------------------------------------------------
// Kernel A (tensor-core): Wh = h @ W via m16n8k16 fp16, K=128 single-shot.
// Also builds the adj bitmask (folded, grid-strided rows).
// ---------------------------------------------------------------------------
static constexpr int SMEM_WH = (2 * BUF + 512) * 4;   // 71,680 B

__global__ __launch_bounds__(512, 1)
void gat_wh_mma(const float* __restrict__ h, const float* __restrict__ W,
                const float* __restrict__ a, const int* __restrict__ adj) {
    extern __shared__ uint32_t smu[];
    uint32_t* hs = smu;                  // [row 128][k half2 34] stride 68
    uint32_t* Ws = smu + BUF;            // [k 128][d half2 34] stride 68
    float* a_sh  = (float*)(smu + 2 * BUF);
    float* es_sm = a_sh + 256;
    float* ed_sm = es_sm + 128;

    int t = threadIdx.x, w = t >> 5, l = t & 31;
    long brow = (long)blockIdx.x * 128;

    // Folded adjmask: CTA handles adj rows blockIdx.x, +gridDim.x, ...
    for (int r = blockIdx.x; r < 512; r += gridDim.x) {
        int v = adj[r * 512 + t];
        unsigned m = __ballot_sync(0xffffffffu, v > 0);
        if (l == 0) g_adjmask[r * 16 + w] = m;
    }

    if (t < 256) a_sh[t] = a[t];
    if (t < 128) { es_sm[t] = 0.f; ed_sm[t] = 0.f; }

    {
        const float4* hg = (const float4*)(h + brow * 128);
        const float4* Wg = (const float4*)W;
#pragma unroll
        for (int m = 0; m < 8; m++) {
            int idx = t + m * 512;               // 0..4095
            int r = idx >> 5, c4 = idx & 31;
            float4 v = hg[idx];
            uint2 st;
            __half2 p0 = __floats2half2_rn(v.x, v.y);
            __half2 p1 = __floats2half2_rn(v.z, v.w);
            st.x = *(uint32_t*)&p0; st.y = *(uint32_t*)&p1;
            *(uint2*)&hs[r * SPH + 2 * c4] = st;

            float4 wv = Wg[idx];
            __half2 q0 = __floats2half2_rn(wv.x, wv.y);
            __half2 q1 = __floats2half2_rn(wv.z, wv.w);
            st.x = *(uint32_t*)&q0; st.y = *(uint32_t*)&q1;
            *(uint2*)&Ws[r * SPH + 2 * c4] = st;
        }
    }
    __syncthreads();

    int wm = w >> 2, wn = w & 3;
    int gid = l >> 2, tig = l & 3;

    uint32_t hs_addr, ws_addr;
    asm("{ .reg .u64 tt; cvta.to.shared.u64 tt, %1; cvt.u32.u64 %0, tt; }"
        : "=r"(hs_addr) : "l"((const void*)hs));
    asm("{ .reg .u64 tt; cvta.to.shared.u64 tt, %1; cvt.u32.u64 %0, tt; }"
        : "=r"(ws_addr) : "l"((const void*)Ws));

    uint32_t a_lane = (uint32_t)((wm * 32 + (l & 7) + 8 * ((l >> 3) & 1)) * SPH
                                 + 4 * (l >> 4)) * 4u;
    uint32_t b_lane = (uint32_t)(((l & 7) + 8 * ((l >> 3) & 1)) * SPH) * 4u
                    + (uint32_t)(wn * 32 + 8 * (l >> 4)) * 2u;

    float acc[2][4][4];
#pragma unroll
    for (int mt = 0; mt < 2; mt++)
#pragma unroll
        for (int nt = 0; nt < 4; nt++)
#pragma unroll
            for (int e = 0; e < 4; e++) acc[mt][nt][e] = 0.f;

    uint32_t pa = hs_addr + a_lane;
    uint32_t ba = ws_addr + b_lane;
    const uint32_t mt_step = 16 * SPH * 4;
#pragma unroll
    for (int ks = 0; ks < 8; ks++) {
        uint32_t A0[4], A1[4], B0[4], B1[4];
        LDSM_X4(A0, pa);
        LDSM_X4(A1, pa + mt_step);
        LDSM_X4_T(B0, ba);
        LDSM_X4_T(B1, ba + 32);          // +16 d halves
        uint32_t* Af[2] = {A0, A1};
        uint32_t Bf[4][2] = {{B0[0], B0[1]}, {B0[2], B0[3]},
                             {B1[0], B1[1]}, {B1[2], B1[3]}};
#pragma unroll
        for (int mt = 0; mt < 2; mt++)
#pragma unroll
            for (int nt = 0; nt < 4; nt++)
                mma_f16(acc[mt][nt], Af[mt], Bf[nt]);
        pa += 32;                        // k += 16 halves
        ba += 16 * SPH * 4;              // k rows += 16
    }

#pragma unroll
    for (int mt = 0; mt < 2; mt++) {
        int r0 = wm * 32 + mt * 16 + gid;
        int r1 = r0 + 8;
        float s0 = 0.f, d0 = 0.f, s1 = 0.f, d1 = 0.f;
#pragma unroll
        for (int nt = 0; nt < 4; nt++) {
            int col = wn * 32 + nt * 8 + 2 * tig;
            __half2 v0 = __floats2half2_rn(acc[mt][nt][0], acc[mt][nt][1]);
            __half2 v1 = __floats2half2_rn(acc[mt][nt][2], acc[mt][nt][3]);
            *(__half2*)(g_Wh + (brow + r0) * 128 + col) = v0;
            *(__half2*)(g_Wh + (brow + r1) * 128 + col) = v1;
            s0 += acc[mt][nt][0] * a_sh[col] + acc[mt][nt][1] * a_sh[col + 1];
            d0 += acc[mt][nt][0] * a_sh[128 + col] + acc[mt][nt][1] * a_sh[128 + col + 1];
            s1 += acc[mt][nt][2] * a_sh[col] + acc[mt][nt][3] * a_sh[col + 1];
            d1 += acc[mt][nt][2] * a_sh[128 + col] + acc[mt][nt][3] * a_sh[128 + col + 1];
        }
#pragma unroll
        for (int o = 1; o <= 2; o <<= 1) {
            s0 += __shfl_xor_sync(0xffffffffu, s0, o);
            d0 += __shfl_xor_sync(0xffffffffu, d0, o);
            s1 += __shfl_xor_sync(0xffffffffu, s1, o);
            d1 += __shfl_xor_sync(0xffffffffu, d1, o);
        }
        if (tig == 0) {
            atomicAdd(es_sm + r0, s0); atomicAdd(ed_sm + r0, d0);
            atomicAdd(es_sm + r1, s1); atomicAdd(ed_sm + r1, d1);
        }
    }
    __syncthreads();
    if (t < 128) {
        g_es[brow + t] = es_sm[t];
        g_ed[brow + t] = ed_sm[t];
    }
}

// ---------------------------------------------------------------------------
// Kernel B: 64 i-rows per CTA, 256 threads / 8 warps (warp tile 32x32),
// 2 CTAs/SM. Double-buffered Ps(64)/Bs(128); role-alternating warps;
// cp.async B staging; adj bitmask; __expf.
// ---------------------------------------------------------------------------
static constexpr int SMEM_ATTN = (2 * BUFP + 2 * BUF + 64) * 4;   // 104,704 B

__global__ __launch_bounds__(256, 2)
void gat_attn_mma(float* __restrict__ out) {
    extern __shared__ uint32_t smu[];
    uint32_t* Ps = smu;                   // 2 x [i 64][k half2 34] stride 68
    uint32_t* Bs = smu + 2 * BUFP;        // 2 x [k 128][d half2 34] stride 68
    float* l_sh = (float*)(smu + 2 * BUFP + 2 * BUF);

    int t = threadIdx.x;
    int w = t >> 5;
    int l = t & 31;
    int bt = blockIdx.x >> 3;
    int ibase = (blockIdx.x & 7) * 64;
    long rowbase = (long)bt * 512;

    if (t < 64) l_sh[t] = 0.f;

    // P-build mapping: thread t -> row t>>2 (0..63), j quarter (t&3)*32
    int i_row = t >> 2;
    int jbase = (t & 3) * 32;
    int kkb = (t & 3) * 16;
    float es_i = g_es[rowbase + ibase + i_row];

    // MMA mapping: 8 warps, wm = w>>2 (0..1), wn = w&3
    int wm = w >> 2, wn = w & 3;
    int gid = l >> 2, tig = l & 3;

    const __half* Whb = g_Wh + rowbase * 128;

    uint32_t ps_addr, bs_addr;
    asm("{ .reg .u64 tt; cvta.to.shared.u64 tt, %1; cvt.u32.u64 %0, tt; }"
        : "=r"(ps_addr) : "l"((const void*)Ps));
    asm("{ .reg .u64 tt; cvta.to.shared.u64 tt, %1; cvt.u32.u64 %0, tt; }"
        : "=r"(bs_addr) : "l"((const void*)Bs));

    uint32_t a_lane = (uint32_t)((wm * 32 + (l & 7) + 8 * ((l >> 3) & 1)) * SPH
                                 + 4 * (l >> 4)) * 4u;
    uint32_t b_lane = (uint32_t)(((l & 7) + 8 * ((l >> 3) & 1)) * SPH) * 4u
                    + (uint32_t)(wn * 32 + 8 * (l >> 4)) * 2u;

    float acc[2][4][4];
#pragma unroll
    for (int mt = 0; mt < 2; mt++)
#pragma unroll
        for (int nt = 0; nt < 4; nt++)
#pragma unroll
            for (int e = 0; e < 4; e++) acc[mt][nt][e] = 0.f;

    auto stage_B = [&](int jt, int buf) {
#pragma unroll
        for (int m = 0; m < 8; m++) {
            int idx = t + m * 256;
            int j = idx >> 4, ch = idx & 15;
            uint32_t dst = bs_addr + (uint32_t)(buf * BUF * 4 + j * SPH * 4 + ch * 16);
            const void* src = Whb + (long)(jt * 128 + j) * 128 + ch * 8;
            asm volatile("cp.async.ca.shared.global [%0], [%1], 16;" :: "r"(dst), "l"(src));
        }
        asm volatile("cp.async.commit_group;" ::: "memory");
    };

    auto build_P = [&](int jt, int buf) {
        uint32_t* Pb = Ps + buf * BUFP;
        float lsum = 0.f;
        uint32_t mask = g_adjmask[(ibase + i_row) * 16 + jt * 4 + (t & 3)];
        const float4* edp = (const float4*)(g_ed + rowbase + jt * 128 + jbase);
#pragma unroll
        for (int c = 0; c < 8; c++) {
            float4 edv = __ldg(edp + c);
            float x, p0, p1, p2, p3;
            x = es_i + edv.x; x = fmaxf(x, ALPHA * x); p0 = (mask >> (4 * c))     & 1 ? __expf(x) : 0.f;
            x = es_i + edv.y; x = fmaxf(x, ALPHA * x); p1 = (mask >> (4 * c + 1)) & 1 ? __expf(x) : 0.f;
            x = es_i + edv.z; x = fmaxf(x, ALPHA * x); p2 = (mask >> (4 * c + 2)) & 1 ? __expf(x) : 0.f;
            x = es_i + edv.w; x = fmaxf(x, ALPHA * x); p3 = (mask >> (4 * c + 3)) & 1 ? __expf(x) : 0.f;
            lsum += p0 + p1 + p2 + p3;
            __half2 h01 = __float22half2_rn(make_float2(p0, p1));
            __half2 h23 = __float22half2_rn(make_float2(p2, p3));
            uint2 st;
            st.x = *(uint32_t*)&h01;
            st.y = *(uint32_t*)&h23;
            *(uint2*)&Pb[i_row * SPH + kkb + 2 * c] = st;
        }
        lsum += __shfl_xor_sync(0xffffffffu, lsum, 1);
        lsum += __shfl_xor_sync(0xffffffffu, lsum, 2);
        if ((t & 3) == 0) l_sh[i_row] += lsum;
    };

    auto do_mma = [&](int buf) {
        uint32_t pa = ps_addr + (uint32_t)(buf * BUFP * 4) + a_lane;
        uint32_t ba = bs_addr + (uint32_t)(buf * BUF * 4) + b_lane;
        const uint32_t mt_step = 16 * SPH * 4;
#pragma unroll
        for (int ks = 0; ks < 8; ks++) {
            uint32_t A0[4], A1[4], B0[4], B1[4];
            LDSM_X4(A0, pa);
            LDSM_X4(A1, pa + mt_step);
            LDSM_X4_T(B0, ba);
            LDSM_X4_T(B1, ba + 32);
            uint32_t* Af[2] = {A0, A1};
            uint32_t Bf[4][2] = {{B0[0], B0[1]}, {B0[2], B0[3]},
                                 {B1[0], B1[1]}, {B1[2], B1[3]}};
#pragma unroll
            for (int mt = 0; mt < 2; mt++)
#pragma unroll
                for (int nt = 0; nt < 4; nt++)
                    mma_f16(acc[mt][nt], Af[mt], Bf[nt]);
            pa += 32;               // k += 16 halves
            ba += 16 * SPH * 4;     // k rows += 16
        }
    };

    __syncthreads();   // l_sh init visible before first build_P

    stage_B(0, 0);
    build_P(0, 0);
    asm volatile("cp.async.wait_group 0;" ::: "memory");
    __syncthreads();

    for (int jt = 0; jt < 4; jt++) {
        int buf = jt & 1, nbuf = buf ^ 1;
        if (jt < 3) stage_B(jt + 1, nbuf);
        if (w & 1) {
            if (jt < 3) build_P(jt + 1, nbuf);
            do_mma(buf);
        } else {
            do_mma(buf);
            if (jt < 3) build_P(jt + 1, nbuf);
        }
        asm volatile("cp.async.wait_group 0;" ::: "memory");
        __syncthreads();
    }

    // Epilogue: out = acc / l.  (acc rows: wm*32 + mt*16 + gid, +8)
#pragma unroll
    for (int mt = 0; mt < 2; mt++) {
        int rb = wm * 32 + mt * 16;
        float inv0 = 1.f / l_sh[rb + gid];
        float inv1 = 1.f / l_sh[rb + gid + 8];
        long row0 = rowbase + ibase + rb + gid;
        long row1 = row0 + 8;
#pragma unroll
        for (int nt = 0; nt < 4; nt++) {
            int col = wn * 32 + nt * 8 + 2 * tig;
            *(float2*)(out + row0 * 128 + col) =
                make_float2(acc[mt][nt][0] * inv0, acc[mt][nt][1] * inv0);
            *(float2*)(out + row1 * 128 + col) =
                make_float2(acc[mt][nt][2] * inv1, acc[mt][nt][3] * inv1);
        }
    }
}

extern "C" void kernel_launch(void* const* d_in, const int* in_sizes, int n_in,
                              void* d_out, int out_size) {
    const float* h   = (const float*)d_in[0];
    const int*   adj = (const int*)d_in[1];
    const float* W   = (const float*)d_in[2];
    const float* a   = (const float*)d_in[3];
    float* out = (float*)d_out;

    int BT = in_sizes[0] / (512 * 128);
    if (BT > 128) BT = 128;

    cudaFuncSetAttribute(gat_wh_mma,
                         cudaFuncAttributeMaxDynamicSharedMemorySize, SMEM_WH);
    cudaFuncSetAttribute(gat_attn_mma,
                         cudaFuncAttributeMaxDynamicSharedMemorySize, SMEM_ATTN);

    gat_wh_mma<<<BT * 4, 512, SMEM_WH>>>(h, W, a, adj);
    gat_attn_mma<<<BT * 8, 256, SMEM_ATTN>>>(out);
}

// round 13
// speedup vs baseline: 4.2191x; 1.0887x over previous
#include <cuda_runtime.h>
#include <cuda_fp16.h>
#include <cstdint>

#define ALPHA 0.2f
#define LOG2E 1.4426950408889634f

// Scratch: max BT = 128 slices. g_Wh layout: [row(65536)][d(128)], fp16.
// g_es/g_ed are PRE-SCALED by log2(e).
__device__ __half g_Wh[128 * 512 * 128];
__device__ float g_es[128 * 512];
__device__ float g_ed[128 * 512];
__device__ uint32_t g_adjmask[512 * 16];   // row i, word w = bits j=32w..32w+31

// ---------------------------------------------------------------------------
// helpers
// ---------------------------------------------------------------------------
__device__ __forceinline__ float ex2(float x) {
    float r;
    asm("ex2.approx.f32 %0, %1;" : "=f"(r) : "f"(x));
    return r;
}

__device__ __forceinline__ void mma_f16(float* d, const uint32_t* a, const uint32_t* b) {
    asm volatile(
        "mma.sync.aligned.m16n8k16.row.col.f32.f16.f16.f32 "
        "{%0,%1,%2,%3}, {%4,%5,%6,%7}, {%8,%9}, {%0,%1,%2,%3};"
        : "+f"(d[0]), "+f"(d[1]), "+f"(d[2]), "+f"(d[3])
        : "r"(a[0]), "r"(a[1]), "r"(a[2]), "r"(a[3]), "r"(b[0]), "r"(b[1]));
}

#define LDSM_X4(r, addr) \
    asm volatile("ldmatrix.sync.aligned.m8n8.x4.shared.b16 {%0,%1,%2,%3}, [%4];" \
        : "=r"((r)[0]), "=r"((r)[1]), "=r"((r)[2]), "=r"((r)[3]) : "r"(addr))

#define LDSM_X4_T(r, addr) \
    asm volatile("ldmatrix.sync.aligned.m8n8.x4.trans.shared.b16 {%0,%1,%2,%3}, [%4];" \
        : "=r"((r)[0]), "=r"((r)[1]), "=r"((r)[2]), "=r"((r)[3]) : "r"(addr))

static constexpr int SPH = 68;            // u32 (half2) row stride for MMA tiles
static constexpr int BUF = 128 * SPH;     // u32 per 128-row tile
static constexpr int BUFP = 64 * SPH;     // u32 per 64-row tile

// ---------------------------------------------------------------------------
// Kernel A (tensor-core): Wh = h @ W via m16n8k16 fp16, K=128 single-shot.
// Also builds the adj bitmask (folded, grid-strided rows).
// ---------------------------------------------------------------------------
static constexpr int SMEM_WH = (2 * BUF + 512) * 4;   // 71,680 B

__global__ __launch_bounds__(512, 1)
void gat_wh_mma(const float* __restrict__ h, const float* __restrict__ W,
                const float* __restrict__ a, const int* __restrict__ adj) {
    extern __shared__ uint32_t smu[];
    uint32_t* hs = smu;                  // [row 128][k half2 34] stride 68
    uint32_t* Ws = smu + BUF;            // [k 128][d half2 34] stride 68
    float* a_sh  = (float*)(smu + 2 * BUF);
    float* es_sm = a_sh + 256;
    float* ed_sm = es_sm + 128;

    int t = threadIdx.x, w = t >> 5, l = t & 31;
    long brow = (long)blockIdx.x * 128;

    // Folded adjmask: CTA handles adj rows blockIdx.x, +gridDim.x, ...
    for (int r = blockIdx.x; r < 512; r += gridDim.x) {
        int v = adj[r * 512 + t];
        unsigned m = __ballot_sync(0xffffffffu, v > 0);
        if (l == 0) g_adjmask[r * 16 + w] = m;
    }

    if (t < 256) a_sh[t] = a[t];
    if (t < 128) { es_sm[t] = 0.f; ed_sm[t] = 0.f; }

    {
        const float4* hg = (const float4*)(h + brow * 128);
        const float4* Wg = (const float4*)W;
#pragma unroll
        for (int m = 0; m < 8; m++) {
            int idx = t + m * 512;               // 0..4095
            int r = idx >> 5, c4 = idx & 31;
            float4 v = hg[idx];
            uint2 st;
            __half2 p0 = __floats2half2_rn(v.x, v.y);
            __half2 p1 = __floats2half2_rn(v.z, v.w);
            st.x = *(uint32_t*)&p0; st.y = *(uint32_t*)&p1;
            *(uint2*)&hs[r * SPH + 2 * c4] = st;

            float4 wv = Wg[idx];
            __half2 q0 = __floats2half2_rn(wv.x, wv.y);
            __half2 q1 = __floats2half2_rn(wv.z, wv.w);
            st.x = *(uint32_t*)&q0; st.y = *(uint32_t*)&q1;
            *(uint2*)&Ws[r * SPH + 2 * c4] = st;
        }
    }
    __syncthreads();

    int wm = w >> 2, wn = w & 3;
    int gid = l >> 2, tig = l & 3;

    uint32_t hs_addr, ws_addr;
    asm("{ .reg .u64 tt; cvta.to.shared.u64 tt, %1; cvt.u32.u64 %0, tt; }"
        : "=r"(hs_addr) : "l"((const void*)hs));
    asm("{ .reg .u64 tt; cvta.to.shared.u64 tt, %1; cvt.u32.u64 %0, tt; }"
        : "=r"(ws_addr) : "l"((const void*)Ws));

    uint32_t a_lane = (uint32_t)((wm * 32 + (l & 7) + 8 * ((l >> 3) & 1)) * SPH
                                 + 4 * (l >> 4)) * 4u;
    uint32_t b_lane = (uint32_t)(((l & 7) + 8 * ((l >> 3) & 1)) * SPH) * 4u
                    + (uint32_t)(wn * 32 + 8 * (l >> 4)) * 2u;

    float acc[2][4][4];
#pragma unroll
    for (int mt = 0; mt < 2; mt++)
#pragma unroll
        for (int nt = 0; nt < 4; nt++)
#pragma unroll
            for (int e = 0; e < 4; e++) acc[mt][nt][e] = 0.f;

    uint32_t pa = hs_addr + a_lane;
    uint32_t ba = ws_addr + b_lane;
    const uint32_t mt_step = 16 * SPH * 4;
#pragma unroll
    for (int ks = 0; ks < 8; ks++) {
        uint32_t A0[4], A1[4], B0[4], B1[4];
        LDSM_X4(A0, pa);
        LDSM_X4(A1, pa + mt_step);
        LDSM_X4_T(B0, ba);
        LDSM_X4_T(B1, ba + 32);          // +16 d halves
        uint32_t* Af[2] = {A0, A1};
        uint32_t Bf[4][2] = {{B0[0], B0[1]}, {B0[2], B0[3]},
                             {B1[0], B1[1]}, {B1[2], B1[3]}};
#pragma unroll
        for (int mt = 0; mt < 2; mt++)
#pragma unroll
            for (int nt = 0; nt < 4; nt++)
                mma_f16(acc[mt][nt], Af[mt], Bf[nt]);
        pa += 32;                        // k += 16 halves
        ba += 16 * SPH * 4;              // k rows += 16
    }

#pragma unroll
    for (int mt = 0; mt < 2; mt++) {
        int r0 = wm * 32 + mt * 16 + gid;
        int r1 = r0 + 8;
        float s0 = 0.f, d0 = 0.f, s1 = 0.f, d1 = 0.f;
#pragma unroll
        for (int nt = 0; nt < 4; nt++) {
            int col = wn * 32 + nt * 8 + 2 * tig;
            __half2 v0 = __floats2half2_rn(acc[mt][nt][0], acc[mt][nt][1]);
            __half2 v1 = __floats2half2_rn(acc[mt][nt][2], acc[mt][nt][3]);
            *(__half2*)(g_Wh + (brow + r0) * 128 + col) = v0;
            *(__half2*)(g_Wh + (brow + r1) * 128 + col) = v1;
            s0 += acc[mt][nt][0] * a_sh[col] + acc[mt][nt][1] * a_sh[col + 1];
            d0 += acc[mt][nt][0] * a_sh[128 + col] + acc[mt][nt][1] * a_sh[128 + col + 1];
            s1 += acc[mt][nt][2] * a_sh[col] + acc[mt][nt][3] * a_sh[col + 1];
            d1 += acc[mt][nt][2] * a_sh[128 + col] + acc[mt][nt][3] * a_sh[128 + col + 1];
        }
#pragma unroll
        for (int o = 1; o <= 2; o <<= 1) {
            s0 += __shfl_xor_sync(0xffffffffu, s0, o);
            d0 += __shfl_xor_sync(0xffffffffu, d0, o);
            s1 += __shfl_xor_sync(0xffffffffu, s1, o);
            d1 += __shfl_xor_sync(0xffffffffu, d1, o);
        }
        if (tig == 0) {
            atomicAdd(es_sm + r0, s0); atomicAdd(ed_sm + r0, d0);
            atomicAdd(es_sm + r1, s1); atomicAdd(ed_sm + r1, d1);
        }
    }
    __syncthreads();
    if (t < 128) {
        g_es[brow + t] = es_sm[t] * LOG2E;   // pre-scaled for ex2
        g_ed[brow + t] = ed_sm[t] * LOG2E;
    }
}

// ---------------------------------------------------------------------------
// Kernel B: 64 i-rows per CTA, 256 threads / 8 warps, 2 CTAs/SM.
// Double-buffered Ps(64)/Bs(128); role-alternating warps; cp.async.cg B
// staging (L1 bypass); mask+ed preloaded to smem; ex2.approx exp.
// ---------------------------------------------------------------------------
static constexpr int MASK_OFF = 2 * BUFP + 2 * BUF;       // u32 idx
static constexpr int ED_OFF   = MASK_OFF + 1024;          // 16 quarters x 36 fl
static constexpr int L_OFF    = ED_OFF + 16 * 36;
static constexpr int SMEM_ATTN = (L_OFF + 64) * 4;        // ~111.3 KB

__global__ __launch_bounds__(256, 2)
void gat_attn_mma(float* __restrict__ out) {
    extern __shared__ uint32_t smu[];
    uint32_t* Ps = smu;                   // 2 x [i 64][k half2 34] stride 68
    uint32_t* Bs = smu + 2 * BUFP;        // 2 x [k 128][d half2 34] stride 68
    uint32_t* mask_sm = smu + MASK_OFF;   // [i 64][word 16]
    float* ed_sm = (float*)(smu + ED_OFF);// 16 quarters x (32 + 4 pad)
    float* l_sh = (float*)(smu + L_OFF);

    int t = threadIdx.x;
    int w = t >> 5;
    int l = t & 31;
    int bt = blockIdx.x >> 3;
    int ibase = (blockIdx.x & 7) * 64;
    long rowbase = (long)bt * 512;

    if (t < 64) l_sh[t] = 0.f;

    // Preload mask (64 rows x 16 words) and ed (512 fl, padded quarters).
#pragma unroll
    for (int m = 0; m < 4; m++) {
        int idx = t + m * 256;
        mask_sm[idx] = g_adjmask[ibase * 16 + idx];
    }
#pragma unroll
    for (int m = 0; m < 2; m++) {
        int f = t + m * 256;
        ed_sm[(f >> 5) * 36 + (f & 31)] = g_ed[rowbase + f];
    }

    // P-build mapping: thread t -> row t>>2 (0..63), j quarter (t&3)
    int i_row = t >> 2;
    int kkb = (t & 3) * 16;
    float es_i = g_es[rowbase + ibase + i_row];   // pre-scaled by log2e

    // MMA mapping: 8 warps, wm = w>>2 (0..1), wn = w&3
    int wm = w >> 2, wn = w & 3;
    int gid = l >> 2, tig = l & 3;

    const __half* Whb = g_Wh + rowbase * 128;

    uint32_t ps_addr, bs_addr;
    asm("{ .reg .u64 tt; cvta.to.shared.u64 tt, %1; cvt.u32.u64 %0, tt; }"
        : "=r"(ps_addr) : "l"((const void*)Ps));
    asm("{ .reg .u64 tt; cvta.to.shared.u64 tt, %1; cvt.u32.u64 %0, tt; }"
        : "=r"(bs_addr) : "l"((const void*)Bs));

    uint32_t a_lane = (uint32_t)((wm * 32 + (l & 7) + 8 * ((l >> 3) & 1)) * SPH
                                 + 4 * (l >> 4)) * 4u;
    uint32_t b_lane = (uint32_t)(((l & 7) + 8 * ((l >> 3) & 1)) * SPH) * 4u
                    + (uint32_t)(wn * 32 + 8 * (l >> 4)) * 2u;

    float acc[2][4][4];
#pragma unroll
    for (int mt = 0; mt < 2; mt++)
#pragma unroll
        for (int nt = 0; nt < 4; nt++)
#pragma unroll
            for (int e = 0; e < 4; e++) acc[mt][nt][e] = 0.f;

    auto stage_B = [&](int jt, int buf) {
#pragma unroll
        for (int m = 0; m < 8; m++) {
            int idx = t + m * 256;
            int j = idx >> 4, ch = idx & 15;
            uint32_t dst = bs_addr + (uint32_t)(buf * BUF * 4 + j * SPH * 4 + ch * 16);
            const void* src = Whb + (long)(jt * 128 + j) * 128 + ch * 8;
            asm volatile("cp.async.cg.shared.global [%0], [%1], 16;" :: "r"(dst), "l"(src));
        }
        asm volatile("cp.async.commit_group;" ::: "memory");
    };

    auto build_P = [&](int jt, int buf) {
        uint32_t* Pb = Ps + buf * BUFP;
        float lsum = 0.f;
        uint32_t mask = mask_sm[i_row * 16 + jt * 4 + (t & 3)];
        const float4* edp = (const float4*)(ed_sm + (jt * 4 + (t & 3)) * 36);
#pragma unroll
        for (int c = 0; c < 8; c++) {
            float4 edv = edp[c];
            float x, p0, p1, p2, p3;
            x = es_i + edv.x; x = fmaxf(x, ALPHA * x); p0 = (mask >> (4 * c))     & 1 ? ex2(x) : 0.f;
            x = es_i + edv.y; x = fmaxf(x, ALPHA * x); p1 = (mask >> (4 * c + 1)) & 1 ? ex2(x) : 0.f;
            x = es_i + edv.z; x = fmaxf(x, ALPHA * x); p2 = (mask >> (4 * c + 2)) & 1 ? ex2(x) : 0.f;
            x = es_i + edv.w; x = fmaxf(x, ALPHA * x); p3 = (mask >> (4 * c + 3)) & 1 ? ex2(x) : 0.f;
            lsum += p0 + p1 + p2 + p3;
            __half2 h01 = __float22half2_rn(make_float2(p0, p1));
            __half2 h23 = __float22half2_rn(make_float2(p2, p3));
            uint2 st;
            st.x = *(uint32_t*)&h01;
            st.y = *(uint32_t*)&h23;
            *(uint2*)&Pb[i_row * SPH + kkb + 2 * c] = st;
        }
        lsum += __shfl_xor_sync(0xffffffffu, lsum, 1);
        lsum += __shfl_xor_sync(0xffffffffu, lsum, 2);
        if ((t & 3) == 0) l_sh[i_row] += lsum;
    };

    auto do_mma = [&](int buf) {
        uint32_t pa = ps_addr + (uint32_t)(buf * BUFP * 4) + a_lane;
        uint32_t ba = bs_addr + (uint32_t)(buf * BUF * 4) + b_lane;
        const uint32_t mt_step = 16 * SPH * 4;
#pragma unroll
        for (int ks = 0; ks < 8; ks++) {
            uint32_t A0[4], A1[4], B0[4], B1[4];
            LDSM_X4(A0, pa);
            LDSM_X4(A1, pa + mt_step);
            LDSM_X4_T(B0, ba);
            LDSM_X4_T(B1, ba + 32);
            uint32_t* Af[2] = {A0, A1};
            uint32_t Bf[4][2] = {{B0[0], B0[1]}, {B0[2], B0[3]},
                                 {B1[0], B1[1]}, {B1[2], B1[3]}};
#pragma unroll
            for (int mt = 0; mt < 2; mt++)
#pragma unroll
                for (int nt = 0; nt < 4; nt++)
                    mma_f16(acc[mt][nt], Af[mt], Bf[nt]);
            pa += 32;               // k += 16 halves
            ba += 16 * SPH * 4;     // k rows += 16
        }
    };

    stage_B(0, 0);
    __syncthreads();   // mask_sm/ed_sm/l_sh visible before first build_P

    build_P(0, 0);
    asm volatile("cp.async.wait_group 0;" ::: "memory");
    __syncthreads();

    for (int jt = 0; jt < 4; jt++) {
        int buf = jt & 1, nbuf = buf ^ 1;
        if (jt < 3) stage_B(jt + 1, nbuf);
        if (w & 1) {
            if (jt < 3) build_P(jt + 1, nbuf);
            do_mma(buf);
        } else {
            do_mma(buf);
            if (jt < 3) build_P(jt + 1, nbuf);
        }
        asm volatile("cp.async.wait_group 0;" ::: "memory");
        __syncthreads();
    }

    // Epilogue: out = acc / l.
#pragma unroll
    for (int mt = 0; mt < 2; mt++) {
        int rb = wm * 32 + mt * 16;
        float inv0 = 1.f / l_sh[rb + gid];
        float inv1 = 1.f / l_sh[rb + gid + 8];
        long row0 = rowbase + ibase + rb + gid;
        long row1 = row0 + 8;
#pragma unroll
        for (int nt = 0; nt < 4; nt++) {
            int col = wn * 32 + nt * 8 + 2 * tig;
            *(float2*)(out + row0 * 128 + col) =
                make_float2(acc[mt][nt][0] * inv0, acc[mt][nt][1] * inv0);
            *(float2*)(out + row1 * 128 + col) =
                make_float2(acc[mt][nt][2] * inv1, acc[mt][nt][3] * inv1);
        }
    }
}

extern "C" void kernel_launch(void* const* d_in, const int* in_sizes, int n_in,
                              void* d_out, int out_size) {
    const float* h   = (const float*)d_in[0];
    const int*   adj = (const int*)d_in[1];
    const float* W   = (const float*)d_in[2];
    const float* a   = (const float*)d_in[3];
    float* out = (float*)d_out;

    int BT = in_sizes[0] / (512 * 128);
    if (BT > 128) BT = 128;

    cudaFuncSetAttribute(gat_wh_mma,
                         cudaFuncAttributeMaxDynamicSharedMemorySize, SMEM_WH);
    cudaFuncSetAttribute(gat_attn_mma,
                         cudaFuncAttributeMaxDynamicSharedMemorySize, SMEM_ATTN);

    gat_wh_mma<<<BT * 4, 512, SMEM_WH>>>(h, W, a, adj);
    gat_attn_mma<<<BT * 8, 256, SMEM_ATTN>>>(out);
}